// round 1
// baseline (speedup 1.0000x reference)
#include <cuda_runtime.h>
#include <cuda_bf16.h>
#include <math.h>

// Problem constants
#define S_LEN 1272      // T_MAX + 31*RIGHT = 1024 + 248
#define D_MODEL 512
#define FF_DIM 2048
#define NLAYERS 8
#define UB 248          // number of hard-copied right-context rows/cols
#define LN_EPS 1e-3f

// ---------------- scratch buffers (static device globals; no allocation) ---
__device__ float g_h   [S_LEN * D_MODEL];
__device__ float g_hn  [S_LEN * D_MODEL];
__device__ float g_q   [S_LEN * D_MODEL];
__device__ float g_k   [S_LEN * D_MODEL];
__device__ float g_v   [S_LEN * D_MODEL];
__device__ float g_attn[S_LEN * D_MODEL];   // attn + hn residual
__device__ float g_y   [S_LEN * D_MODEL];   // ln1 output
__device__ float g_ff  [S_LEN * FF_DIM];
__device__ float g_ff2 [S_LEN * D_MODEL];

// ---------------------------------------------------------------- LayerNorm
// One block per row. 256 threads, 2 elements each (D=512).
__global__ void __launch_bounds__(256) ln_kernel(
    const float* __restrict__ in, const float* __restrict__ gamma,
    const float* __restrict__ beta, float* __restrict__ out)
{
    int r = blockIdx.x;
    int t = threadIdx.x;
    const float* row = in + (size_t)r * D_MODEL;
    float x0 = row[t];
    float x1 = row[t + 256];
    float s  = x0 + x1;
    float ss = x0 * x0 + x1 * x1;

    __shared__ float shs[8], shss[8];
    __shared__ float smu, srstd;
    #pragma unroll
    for (int o = 16; o; o >>= 1) {
        s  += __shfl_xor_sync(0xffffffffu, s, o);
        ss += __shfl_xor_sync(0xffffffffu, ss, o);
    }
    int w = t >> 5, lane = t & 31;
    if (lane == 0) { shs[w] = s; shss[w] = ss; }
    __syncthreads();
    if (t == 0) {
        float a = 0.f, c = 0.f;
        #pragma unroll
        for (int i = 0; i < 8; ++i) { a += shs[i]; c += shss[i]; }
        float mu  = a * (1.0f / D_MODEL);
        float var = c * (1.0f / D_MODEL) - mu * mu;
        smu = mu;
        srstd = rsqrtf(var + LN_EPS);
    }
    __syncthreads();
    float mu = smu, rstd = srstd;
    float* orow = out + (size_t)r * D_MODEL;
    orow[t]       = (x0 - mu) * rstd * gamma[t]       + beta[t];
    orow[t + 256] = (x1 - mu) * rstd * gamma[t + 256] + beta[t + 256];
}

// -------------------------------------------------------------------- SGEMM
// C[M,N] = A[M,K] @ B[K,N] + bias[N] (+ res[M,N] if res != nullptr)
// BM=128, BN=64, BK=16, TM=8, TN=4, 256 threads.
#define BM 128
#define BN 64
#define BK 16

__global__ void __launch_bounds__(256) gemm_kernel(
    const float* __restrict__ A, const float* __restrict__ B,
    const float* __restrict__ bias, const float* __restrict__ res,
    float* __restrict__ C, int M, int N, int K)
{
    __shared__ __align__(16) float As[BK][BM + 4];
    __shared__ __align__(16) float Bs[BK][BN];

    int tid = threadIdx.x;
    int tx = tid & 15;   // column group (0..15) -> 4 cols each
    int ty = tid >> 4;   // row group    (0..15) -> 8 rows each
    int m0 = blockIdx.x * BM;
    int n0 = blockIdx.y * BN;

    // A-load mapping: 4 threads per row, float4 each; two 64-row passes.
    int arow = tid >> 2;          // 0..63
    int acol = (tid & 3) << 2;    // 0,4,8,12
    // B-load mapping: one float4 per thread.
    int brow = tid >> 4;          // 0..15
    int bcol = (tid & 15) << 2;   // 0..60

    float acc[8][4];
    #pragma unroll
    for (int i = 0; i < 8; ++i)
        #pragma unroll
        for (int j = 0; j < 4; ++j) acc[i][j] = 0.f;

    for (int k0 = 0; k0 < K; k0 += BK) {
        #pragma unroll
        for (int p = 0; p < 2; ++p) {
            int r  = arow + p * 64;
            int gm = m0 + r;
            float4 va = make_float4(0.f, 0.f, 0.f, 0.f);
            if (gm < M)
                va = *reinterpret_cast<const float4*>(A + (size_t)gm * K + k0 + acol);
            As[acol + 0][r] = va.x;
            As[acol + 1][r] = va.y;
            As[acol + 2][r] = va.z;
            As[acol + 3][r] = va.w;
        }
        float4 vb = *reinterpret_cast<const float4*>(B + (size_t)(k0 + brow) * N + n0 + bcol);
        *reinterpret_cast<float4*>(&Bs[brow][bcol]) = vb;
        __syncthreads();

        #pragma unroll
        for (int kk = 0; kk < BK; ++kk) {
            float4 a0 = *reinterpret_cast<const float4*>(&As[kk][ty * 8]);
            float4 a1 = *reinterpret_cast<const float4*>(&As[kk][ty * 8 + 4]);
            float4 b  = *reinterpret_cast<const float4*>(&Bs[kk][tx * 4]);
            float ra[8] = {a0.x, a0.y, a0.z, a0.w, a1.x, a1.y, a1.z, a1.w};
            float rb[4] = {b.x, b.y, b.z, b.w};
            #pragma unroll
            for (int i = 0; i < 8; ++i)
                #pragma unroll
                for (int j = 0; j < 4; ++j)
                    acc[i][j] = fmaf(ra[i], rb[j], acc[i][j]);
        }
        __syncthreads();
    }

    #pragma unroll
    for (int i = 0; i < 8; ++i) {
        int gm = m0 + ty * 8 + i;
        if (gm >= M) continue;
        #pragma unroll
        for (int j = 0; j < 4; ++j) {
            int gn = n0 + tx * 4 + j;
            float v = acc[i][j] + bias[gn];
            if (res) v += res[(size_t)gm * N + gn];
            C[(size_t)gm * N + gn] = v;
        }
    }
}

// ---------------------------------------------------------- sparse attention
// Emformer mask computed analytically. One block per query row, one warp per
// head. Each query attends <= 60 keys (right-context 8-block + body range).
// Writes attn_out = softmax(QK^T/8) V + hn  (residual onto ln_in output).
__global__ void __launch_bounds__(256) attn_kernel(
    const float* __restrict__ Q, const float* __restrict__ K,
    const float* __restrict__ V, const float* __restrict__ hn,
    float* __restrict__ out)
{
    __shared__ float sc[8][64];
    int q    = blockIdx.x;
    int w    = threadIdx.x >> 5;
    int lane = threadIdx.x & 31;

    int bodyLo, bodyHi, rcLo, rcHi;
    if (q < UB) {
        int qi = q >> 3;                       // chunk index of this rc block
        bodyLo = max(0, 32 * qi - 20);
        bodyHi = 32 * (qi + 1);
        rcLo = qi << 3;
        rcHi = rcLo + 8;
    } else {
        int qb = q - UB;
        int i  = qb >> 5;                      // body chunk index
        bodyLo = max(0, 32 * i - 20);
        bodyHi = 32 * (i + 1);
        if (i < 31) { rcLo = i << 3; rcHi = rcLo + 8; }
        else        { rcLo = 0; rcHi = 0; }
    }
    int nrc = rcHi - rcLo;
    int nb  = bodyHi - bodyLo;
    int nk  = nrc + nb;

    int h64 = w * 64;
    size_t qoff = (size_t)q * D_MODEL + h64;
    float q0 = Q[qoff + lane]      * 0.125f;   // fold 1/sqrt(64)
    float q1 = Q[qoff + 32 + lane] * 0.125f;

    // scores
    for (int jj = 0; jj < nk; ++jj) {
        int kg = (jj < nrc) ? (rcLo + jj) : (UB + bodyLo + (jj - nrc));
        const float* kp = K + (size_t)kg * D_MODEL + h64;
        float d = q0 * kp[lane] + q1 * kp[lane + 32];
        #pragma unroll
        for (int o = 16; o; o >>= 1) d += __shfl_xor_sync(0xffffffffu, d, o);
        if (lane == 0) sc[w][jj] = d;
    }
    __syncwarp();

    // softmax over the nk allowed keys
    float m = -1e30f;
    for (int jj = lane; jj < nk; jj += 32) m = fmaxf(m, sc[w][jj]);
    #pragma unroll
    for (int o = 16; o; o >>= 1) m = fmaxf(m, __shfl_xor_sync(0xffffffffu, m, o));
    float ssum = 0.f;
    for (int jj = lane; jj < nk; jj += 32) {
        float e = __expf(sc[w][jj] - m);
        sc[w][jj] = e;
        ssum += e;
    }
    #pragma unroll
    for (int o = 16; o; o >>= 1) ssum += __shfl_xor_sync(0xffffffffu, ssum, o);
    float inv = 1.0f / ssum;
    __syncwarp();

    // output
    float acc0 = 0.f, acc1 = 0.f;
    for (int jj = 0; jj < nk; ++jj) {
        int kg = (jj < nrc) ? (rcLo + jj) : (UB + bodyLo + (jj - nrc));
        const float* vp = V + (size_t)kg * D_MODEL + h64;
        float p = sc[w][jj];
        acc0 = fmaf(p, vp[lane],      acc0);
        acc1 = fmaf(p, vp[lane + 32], acc1);
    }
    out[qoff + lane]      = acc0 * inv + hn[qoff + lane];
    out[qoff + 32 + lane] = acc1 * inv + hn[qoff + 32 + lane];
}

// ------------------------------------------------------------------- driver
extern "C" void kernel_launch(void* const* d_in, const int* in_sizes, int n_in,
                              void* d_out, int out_size)
{
    (void)in_sizes; (void)n_in; (void)out_size;

    const float* x      = (const float*)d_in[0];
    // d_in[1] is the mask -- computed analytically on device, not read.
    const float* lnin_s = (const float*)d_in[2];
    const float* lnin_b = (const float*)d_in[3];
    const float* wq     = (const float*)d_in[4];
    const float* bq     = (const float*)d_in[5];
    const float* wk     = (const float*)d_in[6];
    const float* bk     = (const float*)d_in[7];
    const float* wv     = (const float*)d_in[8];
    const float* bv     = (const float*)d_in[9];
    const float* ln1_s  = (const float*)d_in[10];
    const float* ln1_b  = (const float*)d_in[11];
    const float* w1     = (const float*)d_in[12];
    const float* b1     = (const float*)d_in[13];
    const float* w2     = (const float*)d_in[14];
    const float* b2     = (const float*)d_in[15];
    const float* ln2_s  = (const float*)d_in[16];
    const float* ln2_b  = (const float*)d_in[17];
    float* out = (float*)d_out;

    float *p_h, *p_hn, *p_q, *p_k, *p_v, *p_attn, *p_y, *p_ff, *p_ff2;
    cudaGetSymbolAddress((void**)&p_h,    g_h);
    cudaGetSymbolAddress((void**)&p_hn,   g_hn);
    cudaGetSymbolAddress((void**)&p_q,    g_q);
    cudaGetSymbolAddress((void**)&p_k,    g_k);
    cudaGetSymbolAddress((void**)&p_v,    g_v);
    cudaGetSymbolAddress((void**)&p_attn, g_attn);
    cudaGetSymbolAddress((void**)&p_y,    g_y);
    cudaGetSymbolAddress((void**)&p_ff,   g_ff);
    cudaGetSymbolAddress((void**)&p_ff2,  g_ff2);

    const int MTILES = (S_LEN + BM - 1) / BM;               // 10
    dim3 gridD (MTILES, D_MODEL / BN);                      // 10 x 8
    dim3 gridFF(MTILES, FF_DIM / BN);                       // 10 x 32
    dim3 blk(256);

    for (int l = 0; l < NLAYERS; ++l) {
        const float* hin = (l == 0) ? x : p_h;
        size_t wD = (size_t)l * D_MODEL * D_MODEL;
        size_t wF = (size_t)l * D_MODEL * FF_DIM;
        size_t oD = (size_t)l * D_MODEL;
        size_t oF = (size_t)l * FF_DIM;

        // ln_in
        ln_kernel<<<S_LEN, blk>>>(hin, lnin_s + oD, lnin_b + oD, p_hn);
        // Q, K, V projections
        gemm_kernel<<<gridD, blk>>>(p_hn, wq + wD, bq + oD, nullptr, p_q,
                                    S_LEN, D_MODEL, D_MODEL);
        gemm_kernel<<<gridD, blk>>>(p_hn, wk + wD, bk + oD, nullptr, p_k,
                                    S_LEN, D_MODEL, D_MODEL);
        gemm_kernel<<<gridD, blk>>>(p_hn, wv + wD, bv + oD, nullptr, p_v,
                                    S_LEN, D_MODEL, D_MODEL);
        // sparse attention (+ residual onto hn)
        attn_kernel<<<S_LEN, blk>>>(p_q, p_k, p_v, p_hn, p_attn);
        // ln1
        ln_kernel<<<S_LEN, blk>>>(p_attn, ln1_s + oD, ln1_b + oD, p_y);
        // FFN (no nonlinearity in source)
        gemm_kernel<<<gridFF, blk>>>(p_y, w1 + wF, b1 + oF, nullptr, p_ff,
                                     S_LEN, FF_DIM, D_MODEL);
        gemm_kernel<<<gridD, blk>>>(p_ff, w2 + wF, b2 + oD, p_attn, p_ff2,
                                    S_LEN, D_MODEL, FF_DIM);
        // ln2 -> next hidden state (final layer writes straight to d_out)
        float* dst = (l == NLAYERS - 1) ? out : p_h;
        ln_kernel<<<S_LEN, blk>>>(p_ff2, ln2_s + oD, ln2_b + oD, dst);
    }
}

// round 3
// speedup vs baseline: 2.7020x; 2.7020x over previous
#include <cuda_runtime.h>
#include <cuda_bf16.h>
#include <stdint.h>
#include <math.h>

// ---------------------------------------------------------------- constants
#define S_LEN   1272
#define S_PAD   1280
#define D_MODEL 512
#define QKV_N   1536
#define FF_DIM  2048
#define NLAYERS 8
#define UB      248
#define LN_EPS  1e-3f

// ---------------------------------------------------------------- scratch
__device__ float g_h   [S_PAD * D_MODEL];
__device__ float g_hn  [S_PAD * D_MODEL];
__device__ float g_attn[S_PAD * D_MODEL];
__device__ float g_y   [S_PAD * D_MODEL];
__device__ float g_ff2 [S_PAD * D_MODEL];
__device__ float g_qkv [S_PAD * QKV_N];
__device__ float g_bqkv[NLAYERS * QKV_N];

__device__ __nv_bfloat16 g_hn_hi[S_PAD * D_MODEL], g_hn_lo[S_PAD * D_MODEL];
__device__ __nv_bfloat16 g_y_hi [S_PAD * D_MODEL], g_y_lo [S_PAD * D_MODEL];
__device__ __nv_bfloat16 g_ff_hi[S_PAD * FF_DIM],  g_ff_lo[S_PAD * FF_DIM];

__device__ __nv_bfloat16 g_wqkv_hi[NLAYERS * QKV_N * D_MODEL];
__device__ __nv_bfloat16 g_wqkv_lo[NLAYERS * QKV_N * D_MODEL];
__device__ __nv_bfloat16 g_w1t_hi [NLAYERS * FF_DIM * D_MODEL];
__device__ __nv_bfloat16 g_w1t_lo [NLAYERS * FF_DIM * D_MODEL];
__device__ __nv_bfloat16 g_w2t_hi [NLAYERS * D_MODEL * FF_DIM];
__device__ __nv_bfloat16 g_w2t_lo [NLAYERS * D_MODEL * FF_DIM];

// ---------------------------------------------------------------- PTX utils
__device__ __forceinline__ uint32_t smem_u32(const void* p) {
    uint32_t a;
    asm("{ .reg .u64 t; cvta.to.shared.u64 t, %1; cvt.u32.u64 %0, t; }"
        : "=r"(a) : "l"(p));
    return a;
}

#define CP16(s, g) \
    asm volatile("cp.async.cg.shared.global [%0], [%1], 16;" :: "r"(s), "l"(g))
#define CP_COMMIT() asm volatile("cp.async.commit_group;" ::: "memory")
#define CP_WAIT2()  asm volatile("cp.async.wait_group 2;" ::: "memory")
#define CP_WAIT0()  asm volatile("cp.async.wait_group 0;" ::: "memory")

#define LDSM4(r0, r1, r2, r3, a) \
    asm volatile("ldmatrix.sync.aligned.m8n8.x4.shared.b16 {%0,%1,%2,%3}, [%4];" \
                 : "=r"(r0), "=r"(r1), "=r"(r2), "=r"(r3) : "r"(a))

#define MMA16816(c, a, b0, b1)                                                \
    asm volatile("mma.sync.aligned.m16n8k16.row.col.f32.bf16.bf16.f32 "       \
                 "{%0,%1,%2,%3}, {%4,%5,%6,%7}, {%8,%9}, {%0,%1,%2,%3};"      \
                 : "+f"((c)[0]), "+f"((c)[1]), "+f"((c)[2]), "+f"((c)[3])     \
                 : "r"((a)[0]), "r"((a)[1]), "r"((a)[2]), "r"((a)[3]),        \
                   "r"(b0), "r"(b1))

// ---------------------------------------------------------------- LayerNorm
__global__ void __launch_bounds__(256) ln_kernel(
    const float* __restrict__ in, const float* __restrict__ gamma,
    const float* __restrict__ beta, float* __restrict__ out,
    __nv_bfloat16* __restrict__ outHi, __nv_bfloat16* __restrict__ outLo)
{
    int r = blockIdx.x;
    int t = threadIdx.x;
    const float* row = in + (size_t)r * D_MODEL;
    float x0 = row[t];
    float x1 = row[t + 256];
    float s  = x0 + x1;
    float ss = x0 * x0 + x1 * x1;

    __shared__ float shs[8], shss[8];
    __shared__ float smu, srstd;
    #pragma unroll
    for (int o = 16; o; o >>= 1) {
        s  += __shfl_xor_sync(0xffffffffu, s, o);
        ss += __shfl_xor_sync(0xffffffffu, ss, o);
    }
    int w = t >> 5, lane = t & 31;
    if (lane == 0) { shs[w] = s; shss[w] = ss; }
    __syncthreads();
    if (t == 0) {
        float a = 0.f, c = 0.f;
        #pragma unroll
        for (int i = 0; i < 8; ++i) { a += shs[i]; c += shss[i]; }
        float mu  = a * (1.0f / D_MODEL);
        float var = c * (1.0f / D_MODEL) - mu * mu;
        smu = mu;
        srstd = rsqrtf(var + LN_EPS);
    }
    __syncthreads();
    float mu = smu, rstd = srstd;
    float y0 = (x0 - mu) * rstd * gamma[t]       + beta[t];
    float y1 = (x1 - mu) * rstd * gamma[t + 256] + beta[t + 256];
    size_t o0 = (size_t)r * D_MODEL + t;
    out[o0]       = y0;
    out[o0 + 256] = y1;
    if (outHi) {
        __nv_bfloat16 h0 = __float2bfloat16(y0);
        __nv_bfloat16 h1 = __float2bfloat16(y1);
        outHi[o0]       = h0;
        outHi[o0 + 256] = h1;
        outLo[o0]       = __float2bfloat16(y0 - __bfloat162float(h0));
        outLo[o0 + 256] = __float2bfloat16(y1 - __bfloat162float(h1));
    }
}

// ---------------------------------------------- weight transpose + bf16 split
__global__ void __launch_bounds__(256) transpose_split(
    const float* __restrict__ src, __nv_bfloat16* __restrict__ dhi,
    __nv_bfloat16* __restrict__ dlo, int K, int N,
    size_t srcLayerStride, size_t dstLayerStride)
{
    __shared__ float t[32][33];
    int l = blockIdx.z;
    src += (size_t)l * srcLayerStride;
    dhi += (size_t)l * dstLayerStride;
    dlo += (size_t)l * dstLayerStride;
    int n0 = blockIdx.x * 32, k0 = blockIdx.y * 32;
    int tx = threadIdx.x, ty = threadIdx.y;
    #pragma unroll
    for (int i = ty; i < 32; i += 8)
        t[i][tx] = src[(size_t)(k0 + i) * N + n0 + tx];
    __syncthreads();
    #pragma unroll
    for (int i = ty; i < 32; i += 8) {
        float v = t[tx][i];
        __nv_bfloat16 h = __float2bfloat16(v);
        size_t o = (size_t)(n0 + i) * K + k0 + tx;
        dhi[o] = h;
        dlo[o] = __float2bfloat16(v - __bfloat162float(h));
    }
}

__global__ void __launch_bounds__(256) concat_bias(
    const float* __restrict__ bq, const float* __restrict__ bk,
    const float* __restrict__ bv, float* __restrict__ dst)
{
    int i = blockIdx.x * 256 + threadIdx.x;
    if (i >= NLAYERS * QKV_N) return;
    int l = i / QKV_N, c = i % QKV_N;
    float v;
    if (c < 512)       v = bq[l * 512 + c];
    else if (c < 1024) v = bk[l * 512 + c - 512];
    else               v = bv[l * 512 + c - 1024];
    dst[i] = v;
}

// ------------------------------------------------------------- mma.sync GEMM
// C[M=1280, N] = split(A) @ split(B)^T + bias (+ res).
// A: [1280][K] bf16 hi/lo. B: [N][K] bf16 hi/lo (pre-transposed weights).
// BM=128, BN=64, BK=32, 3-stage cp.async pipeline, 8 warps (4x2).
#define AHI_OFF 0
#define ALO_OFF 8192
#define BHI_OFF 16384
#define BLO_OFF 20480
#define STAGE_BYTES 24576
#define GEMM_SMEM (3 * STAGE_BYTES)

// swizzled byte offset of (row r, 16B-chunk c) in a 64B-row tile
__device__ __forceinline__ uint32_t phys(int r, int c) {
    return (uint32_t)(r * 64 + ((c ^ (r & 3)) << 4));
}

__global__ void __launch_bounds__(256, 2) gemm_tc(
    const __nv_bfloat16* __restrict__ Ahi, const __nv_bfloat16* __restrict__ Alo,
    const __nv_bfloat16* __restrict__ Bhi, const __nv_bfloat16* __restrict__ Blo,
    const float* __restrict__ bias, const float* __restrict__ res,
    float* __restrict__ outF, __nv_bfloat16* __restrict__ outHi,
    __nv_bfloat16* __restrict__ outLo, int K, int N)
{
    extern __shared__ char smraw[];
    const uint32_t sb = smem_u32(smraw);

    const int tid  = threadIdx.x;
    const int wid  = tid >> 5;
    const int lane = tid & 31;
    const int wm   = wid >> 1;            // 0..3
    const int wn   = wid & 1;             // 0..1
    const int m0   = blockIdx.x * 128;
    const int n0   = blockIdx.y * 64;

    const __nv_bfloat16* a0 = Ahi + (size_t)m0 * K;
    const __nv_bfloat16* a1 = Alo + (size_t)m0 * K;
    const __nv_bfloat16* b0 = Bhi + (size_t)n0 * K;
    const __nv_bfloat16* b1 = Blo + (size_t)n0 * K;

    // load mapping (per 16B chunk): A has 512 chunks, B has 256
    const int aq0 = tid, aq1 = tid + 256;
    const int ar0 = aq0 >> 2, ac0 = aq0 & 3;
    const int ar1 = aq1 >> 2, ac1 = aq1 & 3;
    const int br  = tid >> 2,  bc  = tid & 3;
    const uint32_t sa0 = phys(ar0, ac0), sa1 = phys(ar1, ac1);
    const uint32_t sbo = phys(br, bc);

    float acc[2][4][4];
    #pragma unroll
    for (int i = 0; i < 2; ++i)
        #pragma unroll
        for (int j = 0; j < 4; ++j)
            #pragma unroll
            for (int k = 0; k < 4; ++k) acc[i][j][k] = 0.f;

    const int NC = K >> 5;

    // issue loads for chunk c into stage buffer
    auto issue = [&](int c) {
        const uint32_t st = sb + (uint32_t)(c % 3) * STAGE_BYTES;
        const int k0 = c << 5;
        CP16(st + AHI_OFF + sa0, a0 + (size_t)ar0 * K + k0 + ac0 * 8);
        CP16(st + AHI_OFF + sa1, a0 + (size_t)ar1 * K + k0 + ac1 * 8);
        CP16(st + ALO_OFF + sa0, a1 + (size_t)ar0 * K + k0 + ac0 * 8);
        CP16(st + ALO_OFF + sa1, a1 + (size_t)ar1 * K + k0 + ac1 * 8);
        CP16(st + BHI_OFF + sbo, b0 + (size_t)br * K + k0 + bc * 8);
        CP16(st + BLO_OFF + sbo, b1 + (size_t)br * K + k0 + bc * 8);
    };

    issue(0); CP_COMMIT();
    if (NC > 1) issue(1);
    CP_COMMIT();

    // fragment addressing
    const int lr = lane & 15, lc = lane >> 4;      // A
    const int bg = lane >> 3, bi = lane & 7;       // B
    const int arow0 = wm * 32 + lr;                // A mt=0 row
    const int arow1 = arow0 + 16;                  // A mt=1 row
    const int brow0 = wn * 32 + ((bg >> 1) << 3) + bi;   // B half 0
    const int brow1 = brow0 + 16;                        // B half 1

    for (int c = 0; c < NC; ++c) {
        if (c + 2 < NC) issue(c + 2);
        CP_COMMIT();
        CP_WAIT2();
        __syncthreads();

        const uint32_t st = sb + (uint32_t)(c % 3) * STAGE_BYTES;
        #pragma unroll
        for (int ks = 0; ks < 2; ++ks) {
            const int ca = ks * 2 + lc;
            const int cb = ks * 2 + (bg & 1);
            uint32_t ah0[4], ah1[4], al0[4], al1[4];
            uint32_t bh[4], bl[4];
            LDSM4(ah0[0], ah0[1], ah0[2], ah0[3], st + AHI_OFF + phys(arow0, ca));
            LDSM4(ah1[0], ah1[1], ah1[2], ah1[3], st + AHI_OFF + phys(arow1, ca));
            LDSM4(al0[0], al0[1], al0[2], al0[3], st + ALO_OFF + phys(arow0, ca));
            LDSM4(al1[0], al1[1], al1[2], al1[3], st + ALO_OFF + phys(arow1, ca));
            // bh[0..1]: n-tile 0 (k0-7,k8-15); bh[2..3]: n-tile 1; second LDSM: tiles 2,3
            uint32_t bh2[4], bl2[4];
            LDSM4(bh[0], bh[1], bh[2], bh[3],     st + BHI_OFF + phys(brow0, cb));
            LDSM4(bh2[0], bh2[1], bh2[2], bh2[3], st + BHI_OFF + phys(brow1, cb));
            LDSM4(bl[0], bl[1], bl[2], bl[3],     st + BLO_OFF + phys(brow0, cb));
            LDSM4(bl2[0], bl2[1], bl2[2], bl2[3], st + BLO_OFF + phys(brow1, cb));

            // pass 1: Ahi * Bhi
            MMA16816(acc[0][0], ah0, bh[0],  bh[1]);
            MMA16816(acc[0][1], ah0, bh[2],  bh[3]);
            MMA16816(acc[0][2], ah0, bh2[0], bh2[1]);
            MMA16816(acc[0][3], ah0, bh2[2], bh2[3]);
            MMA16816(acc[1][0], ah1, bh[0],  bh[1]);
            MMA16816(acc[1][1], ah1, bh[2],  bh[3]);
            MMA16816(acc[1][2], ah1, bh2[0], bh2[1]);
            MMA16816(acc[1][3], ah1, bh2[2], bh2[3]);
            // pass 2: Ahi * Blo
            MMA16816(acc[0][0], ah0, bl[0],  bl[1]);
            MMA16816(acc[0][1], ah0, bl[2],  bl[3]);
            MMA16816(acc[0][2], ah0, bl2[0], bl2[1]);
            MMA16816(acc[0][3], ah0, bl2[2], bl2[3]);
            MMA16816(acc[1][0], ah1, bl[0],  bl[1]);
            MMA16816(acc[1][1], ah1, bl[2],  bl[3]);
            MMA16816(acc[1][2], ah1, bl2[0], bl2[1]);
            MMA16816(acc[1][3], ah1, bl2[2], bl2[3]);
            // pass 3: Alo * Bhi
            MMA16816(acc[0][0], al0, bh[0],  bh[1]);
            MMA16816(acc[0][1], al0, bh[2],  bh[3]);
            MMA16816(acc[0][2], al0, bh2[0], bh2[1]);
            MMA16816(acc[0][3], al0, bh2[2], bh2[3]);
            MMA16816(acc[1][0], al1, bh[0],  bh[1]);
            MMA16816(acc[1][1], al1, bh[2],  bh[3]);
            MMA16816(acc[1][2], al1, bh2[0], bh2[1]);
            MMA16816(acc[1][3], al1, bh2[2], bh2[3]);
        }
        __syncthreads();
    }

    // ------------------------------------------------------------- epilogue
    const int erow = (lane >> 2);
    const int ecol = (lane & 3) * 2;
    #pragma unroll
    for (int mt = 0; mt < 2; ++mt) {
        #pragma unroll
        for (int half = 0; half < 2; ++half) {
            const int row = m0 + wm * 32 + mt * 16 + erow + half * 8;
            #pragma unroll
            for (int nt = 0; nt < 4; ++nt) {
                const int col = n0 + wn * 32 + nt * 8 + ecol;
                float v0 = acc[mt][nt][half * 2 + 0] + __ldg(bias + col);
                float v1 = acc[mt][nt][half * 2 + 1] + __ldg(bias + col + 1);
                if (res) {
                    const float2 r2 = *reinterpret_cast<const float2*>(
                        res + (size_t)row * N + col);
                    v0 += r2.x; v1 += r2.y;
                }
                if (outF)
                    *reinterpret_cast<float2*>(outF + (size_t)row * N + col) =
                        make_float2(v0, v1);
                if (outHi) {
                    __nv_bfloat16 h0 = __float2bfloat16(v0);
                    __nv_bfloat16 h1 = __float2bfloat16(v1);
                    __nv_bfloat162 hh; hh.x = h0; hh.y = h1;
                    __nv_bfloat162 ll;
                    ll.x = __float2bfloat16(v0 - __bfloat162float(h0));
                    ll.y = __float2bfloat16(v1 - __bfloat162float(h1));
                    *reinterpret_cast<__nv_bfloat162*>(
                        outHi + (size_t)row * N + col) = hh;
                    *reinterpret_cast<__nv_bfloat162*>(
                        outLo + (size_t)row * N + col) = ll;
                }
            }
        }
    }
}

// ---------------------------------------------------------- sparse attention
__global__ void __launch_bounds__(256) attn_kernel(
    const float* __restrict__ QKV, const float* __restrict__ hn,
    float* __restrict__ out)
{
    __shared__ float sc[8][64];
    int q    = blockIdx.x;
    int w    = threadIdx.x >> 5;
    int lane = threadIdx.x & 31;

    int bodyLo, bodyHi, rcLo, rcHi;
    if (q < UB) {
        int qi = q >> 3;
        bodyLo = max(0, 32 * qi - 20);
        bodyHi = 32 * (qi + 1);
        rcLo = qi << 3;
        rcHi = rcLo + 8;
    } else {
        int qb = q - UB;
        int i  = qb >> 5;
        bodyLo = max(0, 32 * i - 20);
        bodyHi = 32 * (i + 1);
        if (i < 31) { rcLo = i << 3; rcHi = rcLo + 8; }
        else        { rcLo = 0; rcHi = 0; }
    }
    int nrc = rcHi - rcLo;
    int nb  = bodyHi - bodyLo;
    int nk  = nrc + nb;

    int h64 = w * 64;
    size_t qrow = (size_t)q * QKV_N + h64;
    float q0 = QKV[qrow + lane]      * 0.125f;
    float q1 = QKV[qrow + 32 + lane] * 0.125f;

    for (int jj = 0; jj < nk; ++jj) {
        int kg = (jj < nrc) ? (rcLo + jj) : (UB + bodyLo + (jj - nrc));
        const float* kp = QKV + (size_t)kg * QKV_N + 512 + h64;
        float d = q0 * kp[lane] + q1 * kp[lane + 32];
        #pragma unroll
        for (int o = 16; o; o >>= 1) d += __shfl_xor_sync(0xffffffffu, d, o);
        if (lane == 0) sc[w][jj] = d;
    }
    __syncwarp();

    float m = -1e30f;
    for (int jj = lane; jj < nk; jj += 32) m = fmaxf(m, sc[w][jj]);
    #pragma unroll
    for (int o = 16; o; o >>= 1) m = fmaxf(m, __shfl_xor_sync(0xffffffffu, m, o));
    float ssum = 0.f;
    for (int jj = lane; jj < nk; jj += 32) {
        float e = __expf(sc[w][jj] - m);
        sc[w][jj] = e;
        ssum += e;
    }
    #pragma unroll
    for (int o = 16; o; o >>= 1) ssum += __shfl_xor_sync(0xffffffffu, ssum, o);
    float inv = 1.0f / ssum;
    __syncwarp();

    float acc0 = 0.f, acc1 = 0.f;
    for (int jj = 0; jj < nk; ++jj) {
        int kg = (jj < nrc) ? (rcLo + jj) : (UB + bodyLo + (jj - nrc));
        const float* vp = QKV + (size_t)kg * QKV_N + 1024 + h64;
        float p = sc[w][jj];
        acc0 = fmaf(p, vp[lane],      acc0);
        acc1 = fmaf(p, vp[lane + 32], acc1);
    }
    size_t orow = (size_t)q * D_MODEL + h64;
    out[orow + lane]      = acc0 * inv + hn[orow + lane];
    out[orow + 32 + lane] = acc1 * inv + hn[orow + 32 + lane];
}

// ------------------------------------------------------------------- driver
extern "C" void kernel_launch(void* const* d_in, const int* in_sizes, int n_in,
                              void* d_out, int out_size)
{
    (void)in_sizes; (void)n_in; (void)out_size;

    const float* x      = (const float*)d_in[0];
    const float* lnin_s = (const float*)d_in[2];
    const float* lnin_b = (const float*)d_in[3];
    const float* wq     = (const float*)d_in[4];
    const float* bq     = (const float*)d_in[5];
    const float* wk     = (const float*)d_in[6];
    const float* bk     = (const float*)d_in[7];
    const float* wv     = (const float*)d_in[8];
    const float* bv     = (const float*)d_in[9];
    const float* ln1_s  = (const float*)d_in[10];
    const float* ln1_b  = (const float*)d_in[11];
    const float* w1     = (const float*)d_in[12];
    const float* b1     = (const float*)d_in[13];
    const float* w2     = (const float*)d_in[14];
    const float* b2     = (const float*)d_in[15];
    const float* ln2_s  = (const float*)d_in[16];
    const float* ln2_b  = (const float*)d_in[17];
    float* out = (float*)d_out;

    float *p_h, *p_hn, *p_attn, *p_y, *p_ff2, *p_qkv, *p_bqkv;
    __nv_bfloat16 *p_hn_hi, *p_hn_lo, *p_y_hi, *p_y_lo, *p_ff_hi, *p_ff_lo;
    __nv_bfloat16 *p_wqkv_hi, *p_wqkv_lo, *p_w1t_hi, *p_w1t_lo, *p_w2t_hi, *p_w2t_lo;
    cudaGetSymbolAddress((void**)&p_h,    g_h);
    cudaGetSymbolAddress((void**)&p_hn,   g_hn);
    cudaGetSymbolAddress((void**)&p_attn, g_attn);
    cudaGetSymbolAddress((void**)&p_y,    g_y);
    cudaGetSymbolAddress((void**)&p_ff2,  g_ff2);
    cudaGetSymbolAddress((void**)&p_qkv,  g_qkv);
    cudaGetSymbolAddress((void**)&p_bqkv, g_bqkv);
    cudaGetSymbolAddress((void**)&p_hn_hi, g_hn_hi);
    cudaGetSymbolAddress((void**)&p_hn_lo, g_hn_lo);
    cudaGetSymbolAddress((void**)&p_y_hi,  g_y_hi);
    cudaGetSymbolAddress((void**)&p_y_lo,  g_y_lo);
    cudaGetSymbolAddress((void**)&p_ff_hi, g_ff_hi);
    cudaGetSymbolAddress((void**)&p_ff_lo, g_ff_lo);
    cudaGetSymbolAddress((void**)&p_wqkv_hi, g_wqkv_hi);
    cudaGetSymbolAddress((void**)&p_wqkv_lo, g_wqkv_lo);
    cudaGetSymbolAddress((void**)&p_w1t_hi,  g_w1t_hi);
    cudaGetSymbolAddress((void**)&p_w1t_lo,  g_w1t_lo);
    cudaGetSymbolAddress((void**)&p_w2t_hi,  g_w2t_hi);
    cudaGetSymbolAddress((void**)&p_w2t_lo,  g_w2t_lo);

    cudaFuncSetAttribute(gemm_tc, cudaFuncAttributeMaxDynamicSharedMemorySize,
                         GEMM_SMEM);

    // ---- weight prep: transpose + bf16 hi/lo split ----
    dim3 tb(32, 8);
    transpose_split<<<dim3(16, 16, NLAYERS), tb>>>(
        wq, p_wqkv_hi,          p_wqkv_lo,          512, 512,
        (size_t)512 * 512, (size_t)QKV_N * 512);
    transpose_split<<<dim3(16, 16, NLAYERS), tb>>>(
        wk, p_wqkv_hi + 262144, p_wqkv_lo + 262144, 512, 512,
        (size_t)512 * 512, (size_t)QKV_N * 512);
    transpose_split<<<dim3(16, 16, NLAYERS), tb>>>(
        wv, p_wqkv_hi + 524288, p_wqkv_lo + 524288, 512, 512,
        (size_t)512 * 512, (size_t)QKV_N * 512);
    transpose_split<<<dim3(64, 16, NLAYERS), tb>>>(
        w1, p_w1t_hi, p_w1t_lo, 512, 2048,
        (size_t)512 * 2048, (size_t)2048 * 512);
    transpose_split<<<dim3(16, 64, NLAYERS), tb>>>(
        w2, p_w2t_hi, p_w2t_lo, 2048, 512,
        (size_t)2048 * 512, (size_t)512 * 2048);
    concat_bias<<<(NLAYERS * QKV_N + 255) / 256, 256>>>(bq, bk, bv, p_bqkv);

    dim3 blk(256);
    const int MT = S_PAD / 128;   // 10
    for (int l = 0; l < NLAYERS; ++l) {
        const float* hin = (l == 0) ? x : p_h;
        size_t oD = (size_t)l * D_MODEL;
        size_t oF = (size_t)l * FF_DIM;

        ln_kernel<<<S_LEN, blk>>>(hin, lnin_s + oD, lnin_b + oD,
                                  p_hn, p_hn_hi, p_hn_lo);
        // fused QKV: [1280,512] @ [512,1536]
        gemm_tc<<<dim3(MT, QKV_N / 64), blk, GEMM_SMEM>>>(
            p_hn_hi, p_hn_lo,
            p_wqkv_hi + (size_t)l * QKV_N * 512, p_wqkv_lo + (size_t)l * QKV_N * 512,
            p_bqkv + (size_t)l * QKV_N, nullptr,
            p_qkv, nullptr, nullptr, 512, QKV_N);
        attn_kernel<<<S_LEN, blk>>>(p_qkv, p_hn, p_attn);
        ln_kernel<<<S_LEN, blk>>>(p_attn, ln1_s + oD, ln1_b + oD,
                                  p_y, p_y_hi, p_y_lo);
        // FFN1: [1280,512] @ [512,2048] -> hi/lo only
        gemm_tc<<<dim3(MT, FF_DIM / 64), blk, GEMM_SMEM>>>(
            p_y_hi, p_y_lo,
            p_w1t_hi + (size_t)l * FF_DIM * 512, p_w1t_lo + (size_t)l * FF_DIM * 512,
            b1 + oF, nullptr,
            nullptr, p_ff_hi, p_ff_lo, 512, FF_DIM);
        // FFN2: [1280,2048] @ [2048,512] + b2 + attn residual
        gemm_tc<<<dim3(MT, D_MODEL / 64), blk, GEMM_SMEM>>>(
            p_ff_hi, p_ff_lo,
            p_w2t_hi + (size_t)l * D_MODEL * FF_DIM, p_w2t_lo + (size_t)l * D_MODEL * FF_DIM,
            b2 + oD, p_attn,
            p_ff2, nullptr, nullptr, FF_DIM, D_MODEL);
        float* dst = (l == NLAYERS - 1) ? out : p_h;
        ln_kernel<<<S_LEN, blk>>>(p_ff2, ln2_s + oD, ln2_b + oD,
                                  dst, nullptr, nullptr);
    }
}

// round 4
// speedup vs baseline: 2.9326x; 1.0854x over previous
#include <cuda_runtime.h>
#include <cuda_bf16.h>
#include <stdint.h>
#include <math.h>

// ---------------------------------------------------------------- constants
#define S_LEN   1272
#define S_PAD   1280
#define D_MODEL 512
#define QKV_N   1536
#define FF_DIM  2048
#define NLAYERS 8
#define UB      248
#define LN_EPS  1e-3f

// ---------------------------------------------------------------- scratch
__device__ float g_hn  [S_PAD * D_MODEL];
__device__ float g_attn[S_PAD * D_MODEL];
__device__ float g_ff2 [S_PAD * D_MODEL];
__device__ float g_qkv [S_PAD * QKV_N];
__device__ float g_bqkv[NLAYERS * QKV_N];

__device__ __nv_bfloat16 g_hn_hi[S_PAD * D_MODEL], g_hn_lo[S_PAD * D_MODEL];
__device__ __nv_bfloat16 g_y_hi [S_PAD * D_MODEL], g_y_lo [S_PAD * D_MODEL];
__device__ __nv_bfloat16 g_ff_hi[S_PAD * FF_DIM],  g_ff_lo[S_PAD * FF_DIM];

__device__ __nv_bfloat16 g_wqkv_hi[NLAYERS * QKV_N * D_MODEL];
__device__ __nv_bfloat16 g_wqkv_lo[NLAYERS * QKV_N * D_MODEL];
__device__ __nv_bfloat16 g_w1t_hi [NLAYERS * FF_DIM * D_MODEL];
__device__ __nv_bfloat16 g_w1t_lo [NLAYERS * FF_DIM * D_MODEL];
__device__ __nv_bfloat16 g_w2t_hi [NLAYERS * D_MODEL * FF_DIM];
__device__ __nv_bfloat16 g_w2t_lo [NLAYERS * D_MODEL * FF_DIM];

// ---------------------------------------------------------------- PTX utils
__device__ __forceinline__ uint32_t smem_u32(const void* p) {
    uint32_t a;
    asm("{ .reg .u64 t; cvta.to.shared.u64 t, %1; cvt.u32.u64 %0, t; }"
        : "=r"(a) : "l"(p));
    return a;
}

#define CP16(s, g) \
    asm volatile("cp.async.cg.shared.global [%0], [%1], 16;" :: "r"(s), "l"(g))
#define CP_COMMIT() asm volatile("cp.async.commit_group;" ::: "memory")
#define CP_WAIT2()  asm volatile("cp.async.wait_group 2;" ::: "memory")

#define LDSM4(r0, r1, r2, r3, a) \
    asm volatile("ldmatrix.sync.aligned.m8n8.x4.shared.b16 {%0,%1,%2,%3}, [%4];" \
                 : "=r"(r0), "=r"(r1), "=r"(r2), "=r"(r3) : "r"(a))

#define MMA16816(c, a, b0, b1)                                                \
    asm volatile("mma.sync.aligned.m16n8k16.row.col.f32.bf16.bf16.f32 "       \
                 "{%0,%1,%2,%3}, {%4,%5,%6,%7}, {%8,%9}, {%0,%1,%2,%3};"      \
                 : "+f"((c)[0]), "+f"((c)[1]), "+f"((c)[2]), "+f"((c)[3])     \
                 : "r"((a)[0]), "r"((a)[1]), "r"((a)[2]), "r"((a)[3]),        \
                   "r"(b0), "r"(b1))

// ----------------------------------------------------------- block LN reduce
// 256 threads, each contributing 2 values. Returns (mu, rstd).
__device__ __forceinline__ float2 block_meanvar(float x0, float x1,
                                                float* shs, float* shss,
                                                float* smu, float* srstd)
{
    __syncthreads();                    // protect shared reuse across calls
    int t = threadIdx.x;
    float s  = x0 + x1;
    float ss = x0 * x0 + x1 * x1;
    #pragma unroll
    for (int o = 16; o; o >>= 1) {
        s  += __shfl_xor_sync(0xffffffffu, s, o);
        ss += __shfl_xor_sync(0xffffffffu, ss, o);
    }
    int w = t >> 5, lane = t & 31;
    if (lane == 0) { shs[w] = s; shss[w] = ss; }
    __syncthreads();
    if (t == 0) {
        float a = 0.f, c = 0.f;
        #pragma unroll
        for (int i = 0; i < 8; ++i) { a += shs[i]; c += shss[i]; }
        float mu  = a * (1.0f / D_MODEL);
        float var = c * (1.0f / D_MODEL) - mu * mu;
        *smu = mu;
        *srstd = rsqrtf(var + LN_EPS);
    }
    __syncthreads();
    return make_float2(*smu, *srstd);
}

// ---------------------------------------------------------------- LayerNorm
// Single LN: in -> out fp32 + hi/lo (for layer-0 ln_in).
__global__ void __launch_bounds__(256) ln_kernel(
    const float* __restrict__ in, const float* __restrict__ gamma,
    const float* __restrict__ beta, float* __restrict__ out,
    __nv_bfloat16* __restrict__ outHi, __nv_bfloat16* __restrict__ outLo)
{
    __shared__ float shs[8], shss[8], smu, srstd;
    int r = blockIdx.x;
    int t = threadIdx.x;
    const float* row = in + (size_t)r * D_MODEL;
    float x0 = row[t], x1 = row[t + 256];
    float2 mv = block_meanvar(x0, x1, shs, shss, &smu, &srstd);
    float y0 = (x0 - mv.x) * mv.y * gamma[t]       + beta[t];
    float y1 = (x1 - mv.x) * mv.y * gamma[t + 256] + beta[t + 256];
    size_t o0 = (size_t)r * D_MODEL + t;
    out[o0] = y0; out[o0 + 256] = y1;
    __nv_bfloat16 h0 = __float2bfloat16(y0), h1 = __float2bfloat16(y1);
    outHi[o0] = h0; outHi[o0 + 256] = h1;
    outLo[o0]       = __float2bfloat16(y0 - __bfloat162float(h0));
    outLo[o0 + 256] = __float2bfloat16(y1 - __bfloat162float(h1));
}

// Fused ln2 (+ optional output write) + next layer's ln_in (+ hi/lo).
__global__ void __launch_bounds__(256) ln2_lnin_kernel(
    const float* __restrict__ in, const float* __restrict__ g2,
    const float* __restrict__ b2, float* __restrict__ outT,
    const float* __restrict__ gi, const float* __restrict__ bi,
    float* __restrict__ hn, __nv_bfloat16* __restrict__ hnHi,
    __nv_bfloat16* __restrict__ hnLo)
{
    __shared__ float shs[8], shss[8], smu, srstd;
    int r = blockIdx.x;
    int t = threadIdx.x;
    const float* row = in + (size_t)r * D_MODEL;
    float x0 = row[t], x1 = row[t + 256];
    float2 mv = block_meanvar(x0, x1, shs, shss, &smu, &srstd);
    float t0 = (x0 - mv.x) * mv.y * g2[t]       + b2[t];
    float t1 = (x1 - mv.x) * mv.y * g2[t + 256] + b2[t + 256];
    size_t o0 = (size_t)r * D_MODEL + t;
    if (outT) { outT[o0] = t0; outT[o0 + 256] = t1; }
    if (gi) {
        float2 mv2 = block_meanvar(t0, t1, shs, shss, &smu, &srstd);
        float u0 = (t0 - mv2.x) * mv2.y * gi[t]       + bi[t];
        float u1 = (t1 - mv2.x) * mv2.y * gi[t + 256] + bi[t + 256];
        hn[o0] = u0; hn[o0 + 256] = u1;
        __nv_bfloat16 h0 = __float2bfloat16(u0), h1 = __float2bfloat16(u1);
        hnHi[o0] = h0; hnHi[o0 + 256] = h1;
        hnLo[o0]       = __float2bfloat16(u0 - __bfloat162float(h0));
        hnLo[o0 + 256] = __float2bfloat16(u1 - __bfloat162float(h1));
    }
}

// ---------------------------------------------- weight transpose + bf16 split
// src [K][N] fp32 -> dst [N][K] bf16 hi/lo, bf16x2-coalesced writes.
// Tile: 64 (K) x 32 (N). grid = (N/32, K/64, NLAYERS), block (32, 8).
__global__ void __launch_bounds__(256) transpose_split(
    const float* __restrict__ src, __nv_bfloat16* __restrict__ dhi,
    __nv_bfloat16* __restrict__ dlo, int K, int N,
    size_t srcLayerStride, size_t dstLayerStride)
{
    __shared__ float t[64][33];
    int l = blockIdx.z;
    src += (size_t)l * srcLayerStride;
    dhi += (size_t)l * dstLayerStride;
    dlo += (size_t)l * dstLayerStride;
    int n0 = blockIdx.x * 32, k0 = blockIdx.y * 64;
    int tx = threadIdx.x, ty = threadIdx.y;
    #pragma unroll
    for (int kk = ty; kk < 64; kk += 8)
        t[kk][tx] = src[(size_t)(k0 + kk) * N + n0 + tx];
    __syncthreads();
    #pragma unroll
    for (int nn = ty; nn < 32; nn += 8) {
        float v0 = t[2 * tx][nn];
        float v1 = t[2 * tx + 1][nn];
        __nv_bfloat16 h0 = __float2bfloat16(v0);
        __nv_bfloat16 h1 = __float2bfloat16(v1);
        __nv_bfloat162 hh; hh.x = h0; hh.y = h1;
        __nv_bfloat162 ll;
        ll.x = __float2bfloat16(v0 - __bfloat162float(h0));
        ll.y = __float2bfloat16(v1 - __bfloat162float(h1));
        size_t o = (size_t)(n0 + nn) * K + k0 + 2 * tx;
        *reinterpret_cast<__nv_bfloat162*>(dhi + o) = hh;
        *reinterpret_cast<__nv_bfloat162*>(dlo + o) = ll;
    }
}

__global__ void __launch_bounds__(256) concat_bias(
    const float* __restrict__ bq, const float* __restrict__ bk,
    const float* __restrict__ bv, float* __restrict__ dst)
{
    int i = blockIdx.x * 256 + threadIdx.x;
    if (i >= NLAYERS * QKV_N) return;
    int l = i / QKV_N, c = i % QKV_N;
    float v;
    if (c < 512)       v = bq[l * 512 + c];
    else if (c < 1024) v = bk[l * 512 + c - 512];
    else               v = bv[l * 512 + c - 1024];
    dst[i] = v;
}

// ------------------------------------------------------------- mma.sync GEMM
// BM=128, BN=64, BK=32, 4-stage cp.async pipeline (1 barrier/iter), 8 warps.
#define AHI_OFF 0
#define ALO_OFF 8192
#define BHI_OFF 16384
#define BLO_OFF 20480
#define STAGE_BYTES 24576
#define GEMM_SMEM (4 * STAGE_BYTES)

__device__ __forceinline__ uint32_t phys(int r, int c) {
    return (uint32_t)(r * 64 + ((c ^ (r & 3)) << 4));
}

__global__ void __launch_bounds__(256, 2) gemm_tc(
    const __nv_bfloat16* __restrict__ Ahi, const __nv_bfloat16* __restrict__ Alo,
    const __nv_bfloat16* __restrict__ Bhi, const __nv_bfloat16* __restrict__ Blo,
    const float* __restrict__ bias, const float* __restrict__ res,
    float* __restrict__ outF, __nv_bfloat16* __restrict__ outHi,
    __nv_bfloat16* __restrict__ outLo, int K, int N)
{
    extern __shared__ char smraw[];
    const uint32_t sb = smem_u32(smraw);

    const int tid  = threadIdx.x;
    const int wid  = tid >> 5;
    const int lane = tid & 31;
    const int wm   = wid >> 1;
    const int wn   = wid & 1;
    const int m0   = blockIdx.x * 128;
    const int n0   = blockIdx.y * 64;

    const __nv_bfloat16* a0 = Ahi + (size_t)m0 * K;
    const __nv_bfloat16* a1 = Alo + (size_t)m0 * K;
    const __nv_bfloat16* b0 = Bhi + (size_t)n0 * K;
    const __nv_bfloat16* b1 = Blo + (size_t)n0 * K;

    const int aq0 = tid, aq1 = tid + 256;
    const int ar0 = aq0 >> 2, ac0 = aq0 & 3;
    const int ar1 = aq1 >> 2, ac1 = aq1 & 3;
    const int br  = tid >> 2,  bc  = tid & 3;
    const uint32_t sa0 = phys(ar0, ac0), sa1 = phys(ar1, ac1);
    const uint32_t sbo = phys(br, bc);

    float acc[2][4][4];
    #pragma unroll
    for (int i = 0; i < 2; ++i)
        #pragma unroll
        for (int j = 0; j < 4; ++j)
            #pragma unroll
            for (int k = 0; k < 4; ++k) acc[i][j][k] = 0.f;

    const int NC = K >> 5;

    auto issue = [&](int c) {
        const uint32_t st = sb + (uint32_t)(c & 3) * STAGE_BYTES;
        const int k0 = c << 5;
        CP16(st + AHI_OFF + sa0, a0 + (size_t)ar0 * K + k0 + ac0 * 8);
        CP16(st + AHI_OFF + sa1, a0 + (size_t)ar1 * K + k0 + ac1 * 8);
        CP16(st + ALO_OFF + sa0, a1 + (size_t)ar0 * K + k0 + ac0 * 8);
        CP16(st + ALO_OFF + sa1, a1 + (size_t)ar1 * K + k0 + ac1 * 8);
        CP16(st + BHI_OFF + sbo, b0 + (size_t)br * K + k0 + bc * 8);
        CP16(st + BLO_OFF + sbo, b1 + (size_t)br * K + k0 + bc * 8);
    };

    issue(0); CP_COMMIT();
    issue(1); CP_COMMIT();
    issue(2); CP_COMMIT();

    const int lr = lane & 15, lc = lane >> 4;
    const int bg = lane >> 3, bi = lane & 7;
    const int arow0 = wm * 32 + lr;
    const int arow1 = arow0 + 16;
    const int brow0 = wn * 32 + ((bg >> 1) << 3) + bi;
    const int brow1 = brow0 + 16;

    for (int c = 0; c < NC; ++c) {
        CP_WAIT2();
        __syncthreads();

        const uint32_t st = sb + (uint32_t)(c & 3) * STAGE_BYTES;
        #pragma unroll
        for (int ks = 0; ks < 2; ++ks) {
            const int ca = ks * 2 + lc;
            const int cb = ks * 2 + (bg & 1);
            uint32_t ah0[4], ah1[4], al0[4], al1[4];
            uint32_t bh[4], bl[4], bh2[4], bl2[4];
            LDSM4(ah0[0], ah0[1], ah0[2], ah0[3], st + AHI_OFF + phys(arow0, ca));
            LDSM4(ah1[0], ah1[1], ah1[2], ah1[3], st + AHI_OFF + phys(arow1, ca));
            LDSM4(al0[0], al0[1], al0[2], al0[3], st + ALO_OFF + phys(arow0, ca));
            LDSM4(al1[0], al1[1], al1[2], al1[3], st + ALO_OFF + phys(arow1, ca));
            LDSM4(bh[0], bh[1], bh[2], bh[3],     st + BHI_OFF + phys(brow0, cb));
            LDSM4(bh2[0], bh2[1], bh2[2], bh2[3], st + BHI_OFF + phys(brow1, cb));
            LDSM4(bl[0], bl[1], bl[2], bl[3],     st + BLO_OFF + phys(brow0, cb));
            LDSM4(bl2[0], bl2[1], bl2[2], bl2[3], st + BLO_OFF + phys(brow1, cb));

            MMA16816(acc[0][0], ah0, bh[0],  bh[1]);
            MMA16816(acc[0][1], ah0, bh[2],  bh[3]);
            MMA16816(acc[0][2], ah0, bh2[0], bh2[1]);
            MMA16816(acc[0][3], ah0, bh2[2], bh2[3]);
            MMA16816(acc[1][0], ah1, bh[0],  bh[1]);
            MMA16816(acc[1][1], ah1, bh[2],  bh[3]);
            MMA16816(acc[1][2], ah1, bh2[0], bh2[1]);
            MMA16816(acc[1][3], ah1, bh2[2], bh2[3]);

            MMA16816(acc[0][0], ah0, bl[0],  bl[1]);
            MMA16816(acc[0][1], ah0, bl[2],  bl[3]);
            MMA16816(acc[0][2], ah0, bl2[0], bl2[1]);
            MMA16816(acc[0][3], ah0, bl2[2], bl2[3]);
            MMA16816(acc[1][0], ah1, bl[0],  bl[1]);
            MMA16816(acc[1][1], ah1, bl[2],  bl[3]);
            MMA16816(acc[1][2], ah1, bl2[0], bl2[1]);
            MMA16816(acc[1][3], ah1, bl2[2], bl2[3]);

            MMA16816(acc[0][0], al0, bh[0],  bh[1]);
            MMA16816(acc[0][1], al0, bh[2],  bh[3]);
            MMA16816(acc[0][2], al0, bh2[0], bh2[1]);
            MMA16816(acc[0][3], al0, bh2[2], bh2[3]);
            MMA16816(acc[1][0], al1, bh[0],  bh[1]);
            MMA16816(acc[1][1], al1, bh[2],  bh[3]);
            MMA16816(acc[1][2], al1, bh2[0], bh2[1]);
            MMA16816(acc[1][3], al1, bh2[2], bh2[3]);
        }
        if (c + 3 < NC) issue(c + 3);
        CP_COMMIT();
    }

    // ------------------------------------------------------------- epilogue
    const int erow = (lane >> 2);
    const int ecol = (lane & 3) * 2;
    #pragma unroll
    for (int mt = 0; mt < 2; ++mt) {
        #pragma unroll
        for (int half = 0; half < 2; ++half) {
            const int row = m0 + wm * 32 + mt * 16 + erow + half * 8;
            #pragma unroll
            for (int nt = 0; nt < 4; ++nt) {
                const int col = n0 + wn * 32 + nt * 8 + ecol;
                float v0 = acc[mt][nt][half * 2 + 0] + __ldg(bias + col);
                float v1 = acc[mt][nt][half * 2 + 1] + __ldg(bias + col + 1);
                if (res) {
                    const float2 r2 = *reinterpret_cast<const float2*>(
                        res + (size_t)row * N + col);
                    v0 += r2.x; v1 += r2.y;
                }
                if (outF)
                    *reinterpret_cast<float2*>(outF + (size_t)row * N + col) =
                        make_float2(v0, v1);
                if (outHi) {
                    __nv_bfloat16 h0 = __float2bfloat16(v0);
                    __nv_bfloat16 h1 = __float2bfloat16(v1);
                    __nv_bfloat162 hh; hh.x = h0; hh.y = h1;
                    __nv_bfloat162 ll;
                    ll.x = __float2bfloat16(v0 - __bfloat162float(h0));
                    ll.y = __float2bfloat16(v1 - __bfloat162float(h1));
                    *reinterpret_cast<__nv_bfloat162*>(
                        outHi + (size_t)row * N + col) = hh;
                    *reinterpret_cast<__nv_bfloat162*>(
                        outLo + (size_t)row * N + col) = ll;
                }
            }
        }
    }
}

// ------------------------------------------- sparse attention + fused ln1
// Writes g_attn (attn + hn residual, fp32) and y hi/lo = LN1(attn_out).
__global__ void __launch_bounds__(256) attn_ln_kernel(
    const float* __restrict__ QKV, const float* __restrict__ hn,
    const float* __restrict__ g1, const float* __restrict__ b1,
    float* __restrict__ attnOut,
    __nv_bfloat16* __restrict__ yHi, __nv_bfloat16* __restrict__ yLo)
{
    __shared__ float sc[8][64];
    __shared__ float shs[8], shss[8], smu, srstd;
    int q    = blockIdx.x;
    int w    = threadIdx.x >> 5;
    int lane = threadIdx.x & 31;

    int bodyLo, bodyHi, rcLo, rcHi;
    if (q < UB) {
        int qi = q >> 3;
        bodyLo = max(0, 32 * qi - 20);
        bodyHi = 32 * (qi + 1);
        rcLo = qi << 3;
        rcHi = rcLo + 8;
    } else {
        int qb = q - UB;
        int i  = qb >> 5;
        bodyLo = max(0, 32 * i - 20);
        bodyHi = 32 * (i + 1);
        if (i < 31) { rcLo = i << 3; rcHi = rcLo + 8; }
        else        { rcLo = 0; rcHi = 0; }
    }
    int nrc = rcHi - rcLo;
    int nb  = bodyHi - bodyLo;
    int nk  = nrc + nb;

    int h64 = w * 64;
    size_t qrow = (size_t)q * QKV_N + h64;
    float q0 = QKV[qrow + lane]      * 0.125f;
    float q1 = QKV[qrow + 32 + lane] * 0.125f;

    for (int jj = 0; jj < nk; ++jj) {
        int kg = (jj < nrc) ? (rcLo + jj) : (UB + bodyLo + (jj - nrc));
        const float* kp = QKV + (size_t)kg * QKV_N + 512 + h64;
        float d = q0 * kp[lane] + q1 * kp[lane + 32];
        #pragma unroll
        for (int o = 16; o; o >>= 1) d += __shfl_xor_sync(0xffffffffu, d, o);
        if (lane == 0) sc[w][jj] = d;
    }
    __syncwarp();

    float m = -1e30f;
    for (int jj = lane; jj < nk; jj += 32) m = fmaxf(m, sc[w][jj]);
    #pragma unroll
    for (int o = 16; o; o >>= 1) m = fmaxf(m, __shfl_xor_sync(0xffffffffu, m, o));
    float ssum = 0.f;
    for (int jj = lane; jj < nk; jj += 32) {
        float e = __expf(sc[w][jj] - m);
        sc[w][jj] = e;
        ssum += e;
    }
    #pragma unroll
    for (int o = 16; o; o >>= 1) ssum += __shfl_xor_sync(0xffffffffu, ssum, o);
    float inv = 1.0f / ssum;
    __syncwarp();

    float acc0 = 0.f, acc1 = 0.f;
    for (int jj = 0; jj < nk; ++jj) {
        int kg = (jj < nrc) ? (rcLo + jj) : (UB + bodyLo + (jj - nrc));
        const float* vp = QKV + (size_t)kg * QKV_N + 1024 + h64;
        float p = sc[w][jj];
        acc0 = fmaf(p, vp[lane],      acc0);
        acc1 = fmaf(p, vp[lane + 32], acc1);
    }
    size_t orow = (size_t)q * D_MODEL;
    int c0 = h64 + lane, c1 = h64 + 32 + lane;
    float a0 = acc0 * inv + hn[orow + c0];
    float a1 = acc1 * inv + hn[orow + c1];
    attnOut[orow + c0] = a0;
    attnOut[orow + c1] = a1;

    // fused ln1
    float2 mv = block_meanvar(a0, a1, shs, shss, &smu, &srstd);
    float y0 = (a0 - mv.x) * mv.y * g1[c0] + b1[c0];
    float y1 = (a1 - mv.x) * mv.y * g1[c1] + b1[c1];
    __nv_bfloat16 h0 = __float2bfloat16(y0), h1 = __float2bfloat16(y1);
    yHi[orow + c0] = h0;
    yHi[orow + c1] = h1;
    yLo[orow + c0] = __float2bfloat16(y0 - __bfloat162float(h0));
    yLo[orow + c1] = __float2bfloat16(y1 - __bfloat162float(h1));
}

// ------------------------------------------------------------------- driver
extern "C" void kernel_launch(void* const* d_in, const int* in_sizes, int n_in,
                              void* d_out, int out_size)
{
    (void)in_sizes; (void)n_in; (void)out_size;

    const float* x      = (const float*)d_in[0];
    const float* lnin_s = (const float*)d_in[2];
    const float* lnin_b = (const float*)d_in[3];
    const float* wq     = (const float*)d_in[4];
    const float* bq     = (const float*)d_in[5];
    const float* wk     = (const float*)d_in[6];
    const float* bk     = (const float*)d_in[7];
    const float* wv     = (const float*)d_in[8];
    const float* bv     = (const float*)d_in[9];
    const float* ln1_s  = (const float*)d_in[10];
    const float* ln1_b  = (const float*)d_in[11];
    const float* w1     = (const float*)d_in[12];
    const float* b1     = (const float*)d_in[13];
    const float* w2     = (const float*)d_in[14];
    const float* b2     = (const float*)d_in[15];
    const float* ln2_s  = (const float*)d_in[16];
    const float* ln2_b  = (const float*)d_in[17];
    float* out = (float*)d_out;

    float *p_hn, *p_attn, *p_ff2, *p_qkv, *p_bqkv;
    __nv_bfloat16 *p_hn_hi, *p_hn_lo, *p_y_hi, *p_y_lo, *p_ff_hi, *p_ff_lo;
    __nv_bfloat16 *p_wqkv_hi, *p_wqkv_lo, *p_w1t_hi, *p_w1t_lo, *p_w2t_hi, *p_w2t_lo;
    cudaGetSymbolAddress((void**)&p_hn,   g_hn);
    cudaGetSymbolAddress((void**)&p_attn, g_attn);
    cudaGetSymbolAddress((void**)&p_ff2,  g_ff2);
    cudaGetSymbolAddress((void**)&p_qkv,  g_qkv);
    cudaGetSymbolAddress((void**)&p_bqkv, g_bqkv);
    cudaGetSymbolAddress((void**)&p_hn_hi, g_hn_hi);
    cudaGetSymbolAddress((void**)&p_hn_lo, g_hn_lo);
    cudaGetSymbolAddress((void**)&p_y_hi,  g_y_hi);
    cudaGetSymbolAddress((void**)&p_y_lo,  g_y_lo);
    cudaGetSymbolAddress((void**)&p_ff_hi, g_ff_hi);
    cudaGetSymbolAddress((void**)&p_ff_lo, g_ff_lo);
    cudaGetSymbolAddress((void**)&p_wqkv_hi, g_wqkv_hi);
    cudaGetSymbolAddress((void**)&p_wqkv_lo, g_wqkv_lo);
    cudaGetSymbolAddress((void**)&p_w1t_hi,  g_w1t_hi);
    cudaGetSymbolAddress((void**)&p_w1t_lo,  g_w1t_lo);
    cudaGetSymbolAddress((void**)&p_w2t_hi,  g_w2t_hi);
    cudaGetSymbolAddress((void**)&p_w2t_lo,  g_w2t_lo);

    cudaFuncSetAttribute(gemm_tc, cudaFuncAttributeMaxDynamicSharedMemorySize,
                         GEMM_SMEM);

    // ---- weight prep: transpose + bf16 hi/lo split ----
    dim3 tb(32, 8);
    transpose_split<<<dim3(16, 8, NLAYERS), tb>>>(
        wq, p_wqkv_hi,          p_wqkv_lo,          512, 512,
        (size_t)512 * 512, (size_t)QKV_N * 512);
    transpose_split<<<dim3(16, 8, NLAYERS), tb>>>(
        wk, p_wqkv_hi + 262144, p_wqkv_lo + 262144, 512, 512,
        (size_t)512 * 512, (size_t)QKV_N * 512);
    transpose_split<<<dim3(16, 8, NLAYERS), tb>>>(
        wv, p_wqkv_hi + 524288, p_wqkv_lo + 524288, 512, 512,
        (size_t)512 * 512, (size_t)QKV_N * 512);
    transpose_split<<<dim3(64, 8, NLAYERS), tb>>>(
        w1, p_w1t_hi, p_w1t_lo, 512, 2048,
        (size_t)512 * 2048, (size_t)2048 * 512);
    transpose_split<<<dim3(16, 32, NLAYERS), tb>>>(
        w2, p_w2t_hi, p_w2t_lo, 2048, 512,
        (size_t)2048 * 512, (size_t)512 * 2048);
    concat_bias<<<(NLAYERS * QKV_N + 255) / 256, 256>>>(bq, bk, bv, p_bqkv);

    dim3 blk(256);
    const int MT = S_PAD / 128;   // 10
    for (int l = 0; l < NLAYERS; ++l) {
        size_t oD = (size_t)l * D_MODEL;
        size_t oF = (size_t)l * FF_DIM;

        if (l == 0)
            ln_kernel<<<S_LEN, blk>>>(x, lnin_s, lnin_b, p_hn, p_hn_hi, p_hn_lo);

        // fused QKV: [1280,512] @ [512,1536]
        gemm_tc<<<dim3(MT, QKV_N / 64), blk, GEMM_SMEM>>>(
            p_hn_hi, p_hn_lo,
            p_wqkv_hi + (size_t)l * QKV_N * 512, p_wqkv_lo + (size_t)l * QKV_N * 512,
            p_bqkv + (size_t)l * QKV_N, nullptr,
            p_qkv, nullptr, nullptr, 512, QKV_N);
        // attention + residual + fused ln1
        attn_ln_kernel<<<S_LEN, blk>>>(p_qkv, p_hn, ln1_s + oD, ln1_b + oD,
                                       p_attn, p_y_hi, p_y_lo);
        // FFN1: [1280,512] @ [512,2048] -> hi/lo
        gemm_tc<<<dim3(MT, FF_DIM / 64), blk, GEMM_SMEM>>>(
            p_y_hi, p_y_lo,
            p_w1t_hi + (size_t)l * FF_DIM * 512, p_w1t_lo + (size_t)l * FF_DIM * 512,
            b1 + oF, nullptr,
            nullptr, p_ff_hi, p_ff_lo, 512, FF_DIM);
        // FFN2: [1280,2048] @ [2048,512] + b2 + attn residual
        gemm_tc<<<dim3(MT, D_MODEL / 64), blk, GEMM_SMEM>>>(
            p_ff_hi, p_ff_lo,
            p_w2t_hi + (size_t)l * D_MODEL * FF_DIM, p_w2t_lo + (size_t)l * D_MODEL * FF_DIM,
            b2 + oD, p_attn,
            p_ff2, nullptr, nullptr, FF_DIM, D_MODEL);
        // fused ln2 (+ output on last layer) + next layer ln_in
        if (l < NLAYERS - 1) {
            ln2_lnin_kernel<<<S_LEN, blk>>>(
                p_ff2, ln2_s + oD, ln2_b + oD, nullptr,
                lnin_s + oD + D_MODEL, lnin_b + oD + D_MODEL,
                p_hn, p_hn_hi, p_hn_lo);
        } else {
            ln2_lnin_kernel<<<S_LEN, blk>>>(
                p_ff2, ln2_s + oD, ln2_b + oD, out,
                nullptr, nullptr, nullptr, nullptr, nullptr);
        }
    }
}

// round 5
// speedup vs baseline: 3.1931x; 1.0888x over previous
#include <cuda_runtime.h>
#include <cuda_bf16.h>
#include <stdint.h>
#include <math.h>

// ---------------------------------------------------------------- constants
#define S_LEN   1272
#define S_PAD   1280
#define D_MODEL 512
#define QKV_N   1536
#define FF_DIM  2048
#define NLAYERS 8
#define UB      248
#define LN_EPS  1e-3f

// ---------------------------------------------------------------- scratch
__device__ float g_hn  [S_PAD * D_MODEL];
__device__ float g_attn[S_PAD * D_MODEL];
__device__ float g_ff2a[S_PAD * D_MODEL];
__device__ float g_ff2b[S_PAD * D_MODEL];
__device__ float g_qkv [S_PAD * QKV_N];
__device__ float g_bqkv[NLAYERS * QKV_N];

__device__ __nv_bfloat16 g_hn_hi[S_PAD * D_MODEL], g_hn_lo[S_PAD * D_MODEL];
__device__ __nv_bfloat16 g_y_hi [S_PAD * D_MODEL], g_y_lo [S_PAD * D_MODEL];
__device__ __nv_bfloat16 g_ff_hi[S_PAD * FF_DIM],  g_ff_lo[S_PAD * FF_DIM];

__device__ __nv_bfloat16 g_wqkv_hi[NLAYERS * QKV_N * D_MODEL];
__device__ __nv_bfloat16 g_wqkv_lo[NLAYERS * QKV_N * D_MODEL];
__device__ __nv_bfloat16 g_w1t_hi [NLAYERS * FF_DIM * D_MODEL];
__device__ __nv_bfloat16 g_w1t_lo [NLAYERS * FF_DIM * D_MODEL];
__device__ __nv_bfloat16 g_w2t_hi [NLAYERS * D_MODEL * FF_DIM];
__device__ __nv_bfloat16 g_w2t_lo [NLAYERS * D_MODEL * FF_DIM];

// ---------------------------------------------------------------- PTX utils
__device__ __forceinline__ uint32_t smem_u32(const void* p) {
    uint32_t a;
    asm("{ .reg .u64 t; cvta.to.shared.u64 t, %1; cvt.u32.u64 %0, t; }"
        : "=r"(a) : "l"(p));
    return a;
}

#define CP16(s, g) \
    asm volatile("cp.async.cg.shared.global [%0], [%1], 16;" :: "r"(s), "l"(g))
#define CP_COMMIT() asm volatile("cp.async.commit_group;" ::: "memory")
#define CP_WAIT2()  asm volatile("cp.async.wait_group 2;" ::: "memory")

#define LDSM4(r0, r1, r2, r3, a) \
    asm volatile("ldmatrix.sync.aligned.m8n8.x4.shared.b16 {%0,%1,%2,%3}, [%4];" \
                 : "=r"(r0), "=r"(r1), "=r"(r2), "=r"(r3) : "r"(a))

#define MMA16816(c, a, b0, b1)                                                \
    asm volatile("mma.sync.aligned.m16n8k16.row.col.f32.bf16.bf16.f32 "       \
                 "{%0,%1,%2,%3}, {%4,%5,%6,%7}, {%8,%9}, {%0,%1,%2,%3};"      \
                 : "+f"((c)[0]), "+f"((c)[1]), "+f"((c)[2]), "+f"((c)[3])     \
                 : "r"((a)[0]), "r"((a)[1]), "r"((a)[2]), "r"((a)[3]),        \
                   "r"(b0), "r"(b1))

// ----------------------------------------------------------- block LN reduce
__device__ __forceinline__ float2 block_meanvar(float x0, float x1,
                                                float* shs, float* shss,
                                                float* smu, float* srstd)
{
    __syncthreads();
    int t = threadIdx.x;
    float s  = x0 + x1;
    float ss = x0 * x0 + x1 * x1;
    #pragma unroll
    for (int o = 16; o; o >>= 1) {
        s  += __shfl_xor_sync(0xffffffffu, s, o);
        ss += __shfl_xor_sync(0xffffffffu, ss, o);
    }
    int w = t >> 5, lane = t & 31;
    if (lane == 0) { shs[w] = s; shss[w] = ss; }
    __syncthreads();
    if (t == 0) {
        float a = 0.f, c = 0.f;
        #pragma unroll
        for (int i = 0; i < 8; ++i) { a += shs[i]; c += shss[i]; }
        float mu  = a * (1.0f / D_MODEL);
        float var = c * (1.0f / D_MODEL) - mu * mu;
        *smu = mu;
        *srstd = rsqrtf(var + LN_EPS);
    }
    __syncthreads();
    return make_float2(*smu, *srstd);
}

// ---------------------------------------------------------------- LayerNorm
__global__ void __launch_bounds__(256) ln_kernel(
    const float* __restrict__ in, const float* __restrict__ gamma,
    const float* __restrict__ beta, float* __restrict__ out,
    __nv_bfloat16* __restrict__ outHi, __nv_bfloat16* __restrict__ outLo)
{
    __shared__ float shs[8], shss[8], smu, srstd;
    int r = blockIdx.x;
    int t = threadIdx.x;
    const float* row = in + (size_t)r * D_MODEL;
    float x0 = row[t], x1 = row[t + 256];
    float2 mv = block_meanvar(x0, x1, shs, shss, &smu, &srstd);
    float y0 = (x0 - mv.x) * mv.y * gamma[t]       + beta[t];
    float y1 = (x1 - mv.x) * mv.y * gamma[t + 256] + beta[t + 256];
    size_t o0 = (size_t)r * D_MODEL + t;
    if (out) { out[o0] = y0; out[o0 + 256] = y1; }
    __nv_bfloat16 h0 = __float2bfloat16(y0), h1 = __float2bfloat16(y1);
    outHi[o0] = h0; outHi[o0 + 256] = h1;
    outLo[o0]       = __float2bfloat16(y0 - __bfloat162float(h0));
    outLo[o0 + 256] = __float2bfloat16(y1 - __bfloat162float(h1));
}

// Fused: t = LN2(inA+inB); optionally write t; then hn = LN_in(t) (+hi/lo).
__global__ void __launch_bounds__(256) ln2_lnin_kernel(
    const float* __restrict__ inA, const float* __restrict__ inB,
    const float* __restrict__ g2, const float* __restrict__ b2,
    float* __restrict__ outT,
    const float* __restrict__ gi, const float* __restrict__ bi,
    float* __restrict__ hn, __nv_bfloat16* __restrict__ hnHi,
    __nv_bfloat16* __restrict__ hnLo)
{
    __shared__ float shs[8], shss[8], smu, srstd;
    int r = blockIdx.x;
    int t = threadIdx.x;
    size_t o0 = (size_t)r * D_MODEL + t;
    float x0 = inA[o0]       + inB[o0];
    float x1 = inA[o0 + 256] + inB[o0 + 256];
    float2 mv = block_meanvar(x0, x1, shs, shss, &smu, &srstd);
    float t0 = (x0 - mv.x) * mv.y * g2[t]       + b2[t];
    float t1 = (x1 - mv.x) * mv.y * g2[t + 256] + b2[t + 256];
    if (outT) { outT[o0] = t0; outT[o0 + 256] = t1; }
    if (gi) {
        float2 mv2 = block_meanvar(t0, t1, shs, shss, &smu, &srstd);
        float u0 = (t0 - mv2.x) * mv2.y * gi[t]       + bi[t];
        float u1 = (t1 - mv2.x) * mv2.y * gi[t + 256] + bi[t + 256];
        hn[o0] = u0; hn[o0 + 256] = u1;
        __nv_bfloat16 h0 = __float2bfloat16(u0), h1 = __float2bfloat16(u1);
        hnHi[o0] = h0; hnHi[o0 + 256] = h1;
        hnLo[o0]       = __float2bfloat16(u0 - __bfloat162float(h0));
        hnLo[o0 + 256] = __float2bfloat16(u1 - __bfloat162float(h1));
    }
}

// ---------------------------------------------- weight transpose + bf16 split
__global__ void __launch_bounds__(256) transpose_split(
    const float* __restrict__ src, __nv_bfloat16* __restrict__ dhi,
    __nv_bfloat16* __restrict__ dlo, int K, int N,
    size_t srcLayerStride, size_t dstLayerStride)
{
    __shared__ float t[64][33];
    int l = blockIdx.z;
    src += (size_t)l * srcLayerStride;
    dhi += (size_t)l * dstLayerStride;
    dlo += (size_t)l * dstLayerStride;
    int n0 = blockIdx.x * 32, k0 = blockIdx.y * 64;
    int tx = threadIdx.x, ty = threadIdx.y;
    #pragma unroll
    for (int kk = ty; kk < 64; kk += 8)
        t[kk][tx] = src[(size_t)(k0 + kk) * N + n0 + tx];
    __syncthreads();
    #pragma unroll
    for (int nn = ty; nn < 32; nn += 8) {
        float v0 = t[2 * tx][nn];
        float v1 = t[2 * tx + 1][nn];
        __nv_bfloat16 h0 = __float2bfloat16(v0);
        __nv_bfloat16 h1 = __float2bfloat16(v1);
        __nv_bfloat162 hh; hh.x = h0; hh.y = h1;
        __nv_bfloat162 ll;
        ll.x = __float2bfloat16(v0 - __bfloat162float(h0));
        ll.y = __float2bfloat16(v1 - __bfloat162float(h1));
        size_t o = (size_t)(n0 + nn) * K + k0 + 2 * tx;
        *reinterpret_cast<__nv_bfloat162*>(dhi + o) = hh;
        *reinterpret_cast<__nv_bfloat162*>(dlo + o) = ll;
    }
}

__global__ void __launch_bounds__(256) concat_bias(
    const float* __restrict__ bq, const float* __restrict__ bk,
    const float* __restrict__ bv, float* __restrict__ dst)
{
    int i = blockIdx.x * 256 + threadIdx.x;
    if (i >= NLAYERS * QKV_N) return;
    int l = i / QKV_N, c = i % QKV_N;
    float v;
    if (c < 512)       v = bq[l * 512 + c];
    else if (c < 1024) v = bk[l * 512 + c - 512];
    else               v = bv[l * 512 + c - 1024];
    dst[i] = v;
}

// ------------------------------------------------------------- mma.sync GEMM
// BM=128, BN=64, BK=32, 4-stage cp.async pipeline, 8 warps.
// ldK = row stride of A/B; Klen = K elements this CTA accumulates.
// gridDim.z==2 -> split-K: z=0 writes bias+res+acc to outF; z=1 raw acc to outF2.
#define AHI_OFF 0
#define ALO_OFF 8192
#define BHI_OFF 16384
#define BLO_OFF 20480
#define STAGE_BYTES 24576
#define GEMM_SMEM (4 * STAGE_BYTES)

__device__ __forceinline__ uint32_t phys(int r, int c) {
    return (uint32_t)(r * 64 + ((c ^ (r & 3)) << 4));
}

__global__ void __launch_bounds__(256, 2) gemm_tc(
    const __nv_bfloat16* __restrict__ Ahi, const __nv_bfloat16* __restrict__ Alo,
    const __nv_bfloat16* __restrict__ Bhi, const __nv_bfloat16* __restrict__ Blo,
    const float* __restrict__ bias, const float* __restrict__ res,
    float* __restrict__ outF, float* __restrict__ outF2,
    __nv_bfloat16* __restrict__ outHi, __nv_bfloat16* __restrict__ outLo,
    int Klen, int ldK, int N)
{
    extern __shared__ char smraw[];
    const uint32_t sb = smem_u32(smraw);

    const int tid  = threadIdx.x;
    const int wid  = tid >> 5;
    const int lane = tid & 31;
    const int wm   = wid >> 1;
    const int wn   = wid & 1;
    const int m0   = blockIdx.x * 128;
    const int n0   = blockIdx.y * 64;
    const int kz   = blockIdx.z;
    const int koff = kz * Klen;

    const __nv_bfloat16* a0 = Ahi + (size_t)m0 * ldK + koff;
    const __nv_bfloat16* a1 = Alo + (size_t)m0 * ldK + koff;
    const __nv_bfloat16* b0 = Bhi + (size_t)n0 * ldK + koff;
    const __nv_bfloat16* b1 = Blo + (size_t)n0 * ldK + koff;

    const int aq0 = tid, aq1 = tid + 256;
    const int ar0 = aq0 >> 2, ac0 = aq0 & 3;
    const int ar1 = aq1 >> 2, ac1 = aq1 & 3;
    const int br  = tid >> 2,  bc  = tid & 3;
    const uint32_t sa0 = phys(ar0, ac0), sa1 = phys(ar1, ac1);
    const uint32_t sbo = phys(br, bc);

    float acc[2][4][4];
    #pragma unroll
    for (int i = 0; i < 2; ++i)
        #pragma unroll
        for (int j = 0; j < 4; ++j)
            #pragma unroll
            for (int k = 0; k < 4; ++k) acc[i][j][k] = 0.f;

    const int NC = Klen >> 5;

    auto issue = [&](int c) {
        const uint32_t st = sb + (uint32_t)(c & 3) * STAGE_BYTES;
        const int k0 = c << 5;
        CP16(st + AHI_OFF + sa0, a0 + (size_t)ar0 * ldK + k0 + ac0 * 8);
        CP16(st + AHI_OFF + sa1, a0 + (size_t)ar1 * ldK + k0 + ac1 * 8);
        CP16(st + ALO_OFF + sa0, a1 + (size_t)ar0 * ldK + k0 + ac0 * 8);
        CP16(st + ALO_OFF + sa1, a1 + (size_t)ar1 * ldK + k0 + ac1 * 8);
        CP16(st + BHI_OFF + sbo, b0 + (size_t)br * ldK + k0 + bc * 8);
        CP16(st + BLO_OFF + sbo, b1 + (size_t)br * ldK + k0 + bc * 8);
    };

    issue(0); CP_COMMIT();
    issue(1); CP_COMMIT();
    issue(2); CP_COMMIT();

    const int lr = lane & 15, lc = lane >> 4;
    const int bg = lane >> 3, bi = lane & 7;
    const int arow0 = wm * 32 + lr;
    const int arow1 = arow0 + 16;
    const int brow0 = wn * 32 + ((bg >> 1) << 3) + bi;
    const int brow1 = brow0 + 16;

    for (int c = 0; c < NC; ++c) {
        CP_WAIT2();
        __syncthreads();

        const uint32_t st = sb + (uint32_t)(c & 3) * STAGE_BYTES;
        #pragma unroll
        for (int ks = 0; ks < 2; ++ks) {
            const int ca = ks * 2 + lc;
            const int cb = ks * 2 + (bg & 1);
            uint32_t ah0[4], ah1[4], al0[4], al1[4];
            uint32_t bh[4], bl[4], bh2[4], bl2[4];
            LDSM4(ah0[0], ah0[1], ah0[2], ah0[3], st + AHI_OFF + phys(arow0, ca));
            LDSM4(ah1[0], ah1[1], ah1[2], ah1[3], st + AHI_OFF + phys(arow1, ca));
            LDSM4(al0[0], al0[1], al0[2], al0[3], st + ALO_OFF + phys(arow0, ca));
            LDSM4(al1[0], al1[1], al1[2], al1[3], st + ALO_OFF + phys(arow1, ca));
            LDSM4(bh[0], bh[1], bh[2], bh[3],     st + BHI_OFF + phys(brow0, cb));
            LDSM4(bh2[0], bh2[1], bh2[2], bh2[3], st + BHI_OFF + phys(brow1, cb));
            LDSM4(bl[0], bl[1], bl[2], bl[3],     st + BLO_OFF + phys(brow0, cb));
            LDSM4(bl2[0], bl2[1], bl2[2], bl2[3], st + BLO_OFF + phys(brow1, cb));

            MMA16816(acc[0][0], ah0, bh[0],  bh[1]);
            MMA16816(acc[0][1], ah0, bh[2],  bh[3]);
            MMA16816(acc[0][2], ah0, bh2[0], bh2[1]);
            MMA16816(acc[0][3], ah0, bh2[2], bh2[3]);
            MMA16816(acc[1][0], ah1, bh[0],  bh[1]);
            MMA16816(acc[1][1], ah1, bh[2],  bh[3]);
            MMA16816(acc[1][2], ah1, bh2[0], bh2[1]);
            MMA16816(acc[1][3], ah1, bh2[2], bh2[3]);

            MMA16816(acc[0][0], ah0, bl[0],  bl[1]);
            MMA16816(acc[0][1], ah0, bl[2],  bl[3]);
            MMA16816(acc[0][2], ah0, bl2[0], bl2[1]);
            MMA16816(acc[0][3], ah0, bl2[2], bl2[3]);
            MMA16816(acc[1][0], ah1, bl[0],  bl[1]);
            MMA16816(acc[1][1], ah1, bl[2],  bl[3]);
            MMA16816(acc[1][2], ah1, bl2[0], bl2[1]);
            MMA16816(acc[1][3], ah1, bl2[2], bl2[3]);

            MMA16816(acc[0][0], al0, bh[0],  bh[1]);
            MMA16816(acc[0][1], al0, bh[2],  bh[3]);
            MMA16816(acc[0][2], al0, bh2[0], bh2[1]);
            MMA16816(acc[0][3], al0, bh2[2], bh2[3]);
            MMA16816(acc[1][0], al1, bh[0],  bh[1]);
            MMA16816(acc[1][1], al1, bh[2],  bh[3]);
            MMA16816(acc[1][2], al1, bh2[0], bh2[1]);
            MMA16816(acc[1][3], al1, bh2[2], bh2[3]);
        }
        if (c + 3 < NC) issue(c + 3);
        CP_COMMIT();
    }

    // ------------------------------------------------------------- epilogue
    const int erow = (lane >> 2);
    const int ecol = (lane & 3) * 2;
    #pragma unroll
    for (int mt = 0; mt < 2; ++mt) {
        #pragma unroll
        for (int half = 0; half < 2; ++half) {
            const int row = m0 + wm * 32 + mt * 16 + erow + half * 8;
            #pragma unroll
            for (int nt = 0; nt < 4; ++nt) {
                const int col = n0 + wn * 32 + nt * 8 + ecol;
                float v0 = acc[mt][nt][half * 2 + 0];
                float v1 = acc[mt][nt][half * 2 + 1];
                if (kz == 1) {
                    *reinterpret_cast<float2*>(outF2 + (size_t)row * N + col) =
                        make_float2(v0, v1);
                    continue;
                }
                v0 += __ldg(bias + col);
                v1 += __ldg(bias + col + 1);
                if (res) {
                    const float2 r2 = *reinterpret_cast<const float2*>(
                        res + (size_t)row * N + col);
                    v0 += r2.x; v1 += r2.y;
                }
                if (outF)
                    *reinterpret_cast<float2*>(outF + (size_t)row * N + col) =
                        make_float2(v0, v1);
                if (outHi) {
                    __nv_bfloat16 h0 = __float2bfloat16(v0);
                    __nv_bfloat16 h1 = __float2bfloat16(v1);
                    __nv_bfloat162 hh; hh.x = h0; hh.y = h1;
                    __nv_bfloat162 ll;
                    ll.x = __float2bfloat16(v0 - __bfloat162float(h0));
                    ll.y = __float2bfloat16(v1 - __bfloat162float(h1));
                    *reinterpret_cast<__nv_bfloat162*>(
                        outHi + (size_t)row * N + col) = hh;
                    *reinterpret_cast<__nv_bfloat162*>(
                        outLo + (size_t)row * N + col) = ll;
                }
            }
        }
    }
}

// ---------------------------------------------- chunked sparse attention
// One block per (chunk, head). All queries of a chunk share the same key set:
// rc keys [8i, 8i+8) (i<31) + body keys [bodyLo, 32(i+1)). nk <= 60.
// Queries: 8 rc rows (i<31) + 32 body rows. Writes attnOut = PV + hn residual.
__global__ void __launch_bounds__(256) attn_chunk_kernel(
    const float* __restrict__ QKV, const float* __restrict__ hn,
    float* __restrict__ attnOut)
{
    __shared__ float Ks[64][61];   // [dim][key], conflict-free lanes-over-keys
    __shared__ float Vs[60][68];   // [key][dim], float2-aligned rows
    __shared__ float Qs[40][64];   // [query][dim], broadcast reads

    const int i    = blockIdx.x;         // chunk 0..31
    const int h    = blockIdx.y;         // head 0..7
    const int tid  = threadIdx.x;
    const int w    = tid >> 5;
    const int lane = tid & 31;
    const int hoff = h * 64;

    const int bodyLo = max(0, 32 * i - 20);
    const int nb     = 32 * (i + 1) - bodyLo;
    const int nrc    = (i < 31) ? 8 : 0;
    const int nk     = nrc + nb;
    const int nq     = 32 + nrc;

    // stage K (transposed) and V
    for (int e = tid; e < nk * 64; e += 256) {
        int j = e >> 6, d = e & 63;
        int kg = (j < nrc) ? (8 * i + j) : (UB + bodyLo + (j - nrc));
        const float* base = QKV + (size_t)kg * QKV_N + hoff + d;
        Ks[d][j] = base[512];
        Vs[j][d] = base[1024];
    }
    // stage Q (scale folded)
    for (int e = tid; e < nq * 64; e += 256) {
        int qq = e >> 6, d = e & 63;
        int row = (qq < nrc) ? (8 * i + qq) : (UB + 32 * i + (qq - nrc));
        Qs[qq][d] = QKV[(size_t)row * QKV_N + hoff + d] * 0.125f;
    }
    __syncthreads();

    const int perW = nq >> 3;            // 5 (i<31) or 4
    const int lim1 = nk - 32;            // #keys handled via e1 (8..28)

    for (int j = 0; j < perW; ++j) {
        const int qq = w * perW + j;
        // scores: lane handles keys lane and lane+32 (no shuffles)
        float s0 = 0.f, s1 = 0.f;
        #pragma unroll 16
        for (int d = 0; d < 64; ++d) {
            float qd = Qs[qq][d];
            s0 = fmaf(qd, Ks[d][lane],      s0);
            s1 = fmaf(qd, Ks[d][lane + 32], s1);
        }
        if (lane >= lim1) s1 = -1e30f;
        float m = fmaxf(s0, s1);
        #pragma unroll
        for (int o = 16; o; o >>= 1) m = fmaxf(m, __shfl_xor_sync(0xffffffffu, m, o));
        float e0 = __expf(s0 - m);
        float e1 = (lane < lim1) ? __expf(s1 - m) : 0.f;
        float ssum = e0 + e1;
        #pragma unroll
        for (int o = 16; o; o >>= 1) ssum += __shfl_xor_sync(0xffffffffu, ssum, o);
        const float inv = 1.0f / ssum;

        // PV: lane accumulates dims 2*lane, 2*lane+1
        float o0 = 0.f, o1 = 0.f;
        #pragma unroll 8
        for (int jj = 0; jj < 32; ++jj) {
            float p = __shfl_sync(0xffffffffu, e0, jj);
            float2 v = *reinterpret_cast<const float2*>(&Vs[jj][2 * lane]);
            o0 = fmaf(p, v.x, o0);
            o1 = fmaf(p, v.y, o1);
        }
        for (int jj = 0; jj < lim1; ++jj) {
            float p = __shfl_sync(0xffffffffu, e1, jj);
            float2 v = *reinterpret_cast<const float2*>(&Vs[jj + 32][2 * lane]);
            o0 = fmaf(p, v.x, o0);
            o1 = fmaf(p, v.y, o1);
        }
        const int row = (qq < nrc) ? (8 * i + qq) : (UB + 32 * i + (qq - nrc));
        const size_t off = (size_t)row * D_MODEL + hoff + 2 * lane;
        const float2 hv = *reinterpret_cast<const float2*>(hn + off);
        *reinterpret_cast<float2*>(attnOut + off) =
            make_float2(o0 * inv + hv.x, o1 * inv + hv.y);
    }
}

// ------------------------------------------------------------------- driver
extern "C" void kernel_launch(void* const* d_in, const int* in_sizes, int n_in,
                              void* d_out, int out_size)
{
    (void)in_sizes; (void)n_in; (void)out_size;

    const float* x      = (const float*)d_in[0];
    const float* lnin_s = (const float*)d_in[2];
    const float* lnin_b = (const float*)d_in[3];
    const float* wq     = (const float*)d_in[4];
    const float* bq     = (const float*)d_in[5];
    const float* wk     = (const float*)d_in[6];
    const float* bk     = (const float*)d_in[7];
    const float* wv     = (const float*)d_in[8];
    const float* bv     = (const float*)d_in[9];
    const float* ln1_s  = (const float*)d_in[10];
    const float* ln1_b  = (const float*)d_in[11];
    const float* w1     = (const float*)d_in[12];
    const float* b1     = (const float*)d_in[13];
    const float* w2     = (const float*)d_in[14];
    const float* b2     = (const float*)d_in[15];
    const float* ln2_s  = (const float*)d_in[16];
    const float* ln2_b  = (const float*)d_in[17];
    float* out = (float*)d_out;

    float *p_hn, *p_attn, *p_ff2a, *p_ff2b, *p_qkv, *p_bqkv;
    __nv_bfloat16 *p_hn_hi, *p_hn_lo, *p_y_hi, *p_y_lo, *p_ff_hi, *p_ff_lo;
    __nv_bfloat16 *p_wqkv_hi, *p_wqkv_lo, *p_w1t_hi, *p_w1t_lo, *p_w2t_hi, *p_w2t_lo;
    cudaGetSymbolAddress((void**)&p_hn,    g_hn);
    cudaGetSymbolAddress((void**)&p_attn,  g_attn);
    cudaGetSymbolAddress((void**)&p_ff2a,  g_ff2a);
    cudaGetSymbolAddress((void**)&p_ff2b,  g_ff2b);
    cudaGetSymbolAddress((void**)&p_qkv,   g_qkv);
    cudaGetSymbolAddress((void**)&p_bqkv,  g_bqkv);
    cudaGetSymbolAddress((void**)&p_hn_hi, g_hn_hi);
    cudaGetSymbolAddress((void**)&p_hn_lo, g_hn_lo);
    cudaGetSymbolAddress((void**)&p_y_hi,  g_y_hi);
    cudaGetSymbolAddress((void**)&p_y_lo,  g_y_lo);
    cudaGetSymbolAddress((void**)&p_ff_hi, g_ff_hi);
    cudaGetSymbolAddress((void**)&p_ff_lo, g_ff_lo);
    cudaGetSymbolAddress((void**)&p_wqkv_hi, g_wqkv_hi);
    cudaGetSymbolAddress((void**)&p_wqkv_lo, g_wqkv_lo);
    cudaGetSymbolAddress((void**)&p_w1t_hi,  g_w1t_hi);
    cudaGetSymbolAddress((void**)&p_w1t_lo,  g_w1t_lo);
    cudaGetSymbolAddress((void**)&p_w2t_hi,  g_w2t_hi);
    cudaGetSymbolAddress((void**)&p_w2t_lo,  g_w2t_lo);

    cudaFuncSetAttribute(gemm_tc, cudaFuncAttributeMaxDynamicSharedMemorySize,
                         GEMM_SMEM);

    // ---- weight prep: transpose + bf16 hi/lo split ----
    dim3 tb(32, 8);
    transpose_split<<<dim3(16, 8, NLAYERS), tb>>>(
        wq, p_wqkv_hi,          p_wqkv_lo,          512, 512,
        (size_t)512 * 512, (size_t)QKV_N * 512);
    transpose_split<<<dim3(16, 8, NLAYERS), tb>>>(
        wk, p_wqkv_hi + 262144, p_wqkv_lo + 262144, 512, 512,
        (size_t)512 * 512, (size_t)QKV_N * 512);
    transpose_split<<<dim3(16, 8, NLAYERS), tb>>>(
        wv, p_wqkv_hi + 524288, p_wqkv_lo + 524288, 512, 512,
        (size_t)512 * 512, (size_t)QKV_N * 512);
    transpose_split<<<dim3(64, 8, NLAYERS), tb>>>(
        w1, p_w1t_hi, p_w1t_lo, 512, 2048,
        (size_t)512 * 2048, (size_t)2048 * 512);
    transpose_split<<<dim3(16, 32, NLAYERS), tb>>>(
        w2, p_w2t_hi, p_w2t_lo, 2048, 512,
        (size_t)2048 * 512, (size_t)512 * 2048);
    concat_bias<<<(NLAYERS * QKV_N + 255) / 256, 256>>>(bq, bk, bv, p_bqkv);

    dim3 blk(256);
    const int MT = S_PAD / 128;   // 10
    for (int l = 0; l < NLAYERS; ++l) {
        size_t oD = (size_t)l * D_MODEL;
        size_t oF = (size_t)l * FF_DIM;

        if (l == 0)
            ln_kernel<<<S_LEN, blk>>>(x, lnin_s, lnin_b, p_hn, p_hn_hi, p_hn_lo);

        // fused QKV: [1280,512] @ [512,1536]
        gemm_tc<<<dim3(MT, QKV_N / 64), blk, GEMM_SMEM>>>(
            p_hn_hi, p_hn_lo,
            p_wqkv_hi + (size_t)l * QKV_N * 512, p_wqkv_lo + (size_t)l * QKV_N * 512,
            p_bqkv + (size_t)l * QKV_N, nullptr,
            p_qkv, nullptr, nullptr, nullptr, 512, 512, QKV_N);
        // chunked sparse attention (+ residual onto hn)
        attn_chunk_kernel<<<dim3(32, 8), blk>>>(p_qkv, p_hn, p_attn);
        // ln1 -> y hi/lo
        ln_kernel<<<S_LEN, blk>>>(p_attn, ln1_s + oD, ln1_b + oD,
                                  nullptr, p_y_hi, p_y_lo);
        // FFN1: [1280,512] @ [512,2048] -> hi/lo
        gemm_tc<<<dim3(MT, FF_DIM / 64), blk, GEMM_SMEM>>>(
            p_y_hi, p_y_lo,
            p_w1t_hi + (size_t)l * FF_DIM * 512, p_w1t_lo + (size_t)l * FF_DIM * 512,
            b1 + oF, nullptr,
            nullptr, nullptr, p_ff_hi, p_ff_lo, 512, 512, FF_DIM);
        // FFN2 split-K=2: [1280,2048] @ [2048,512]; z=0 adds bias+attn residual
        gemm_tc<<<dim3(MT, D_MODEL / 64, 2), blk, GEMM_SMEM>>>(
            p_ff_hi, p_ff_lo,
            p_w2t_hi + (size_t)l * D_MODEL * FF_DIM, p_w2t_lo + (size_t)l * D_MODEL * FF_DIM,
            b2 + oD, p_attn,
            p_ff2a, p_ff2b, nullptr, nullptr, 1024, FF_DIM, D_MODEL);
        // fused ln2(a+b) (+ output on last layer) + next layer ln_in
        if (l < NLAYERS - 1) {
            ln2_lnin_kernel<<<S_LEN, blk>>>(
                p_ff2a, p_ff2b, ln2_s + oD, ln2_b + oD, nullptr,
                lnin_s + oD + D_MODEL, lnin_b + oD + D_MODEL,
                p_hn, p_hn_hi, p_hn_lo);
        } else {
            ln2_lnin_kernel<<<S_LEN, blk>>>(
                p_ff2a, p_ff2b, ln2_s + oD, ln2_b + oD, out,
                nullptr, nullptr, nullptr, nullptr, nullptr);
        }
    }
}